// round 3
// baseline (speedup 1.0000x reference)
#include <cuda_runtime.h>

// Problem constants
#define Bb 8
#define Nn 512
#define Tt 64
#define Dd 128
#define Hh 8
#define DKk 16
#define Kk 3

#define XS 132                      // padded row stride (floats) for all tiles
#define TILEP (Tt * XS)             // 8448 floats per padded tile
#define WCH 16                      // din chunk
#define STAGE_F TILEP               // stage buffer doubles as x tile (8448 >= 6144)
#define MASK_I (Tt * 65)            // 4160 ints
#define SMEM_FLOATS (3 * TILEP + STAGE_F + MASK_I)   // 37952
#define SMEM_BYTES (SMEM_FLOATS * 4)                 // 151808

typedef unsigned long long ull;

__device__ __forceinline__ ull pk2(float lo, float hi) {
    ull r; asm("mov.b64 %0, {%1,%2};" : "=l"(r) : "f"(lo), "f"(hi)); return r;
}
__device__ __forceinline__ float2 upk2(ull a) {
    float2 f; asm("mov.b64 {%0,%1}, %2;" : "=f"(f.x), "=f"(f.y) : "l"(a)); return f;
}
__device__ __forceinline__ ull fma2(ull a, ull b, ull c) {
    ull d; asm("fma.rn.f32x2 %0, %1, %2, %3;" : "=l"(d) : "l"(a), "l"(b), "l"(c)); return d;
}
__device__ __forceinline__ ull add2(ull a, ull b) {
    ull d; asm("add.rn.f32x2 %0, %1, %2;" : "=l"(d) : "l"(a), "l"(b)); return d;
}

// Pre-transposed weights
__device__ float g_Wq_t[Kk * Dd * Dd];   // [(j*D + din)*D + dout]
__device__ float g_Wk_t[Kk * Dd * Dd];
__device__ float g_Wv_t[Dd * Dd];        // [din*D + e]
__device__ float g_Wo_t[Dd * Dd];

__global__ void prep_kernel(const float* __restrict__ Wq, const float* __restrict__ Wk,
                            const float* __restrict__ Wv, const float* __restrict__ Wo) {
    int i = blockIdx.x * blockDim.x + threadIdx.x;
    const int nConv = Kk * Dd * Dd;  // 49152
    if (i < nConv) {
        int dout = i & (Dd - 1);
        int rem = i >> 7;           // j*D + din
        int din = rem & (Dd - 1);
        int j = rem >> 7;
        g_Wq_t[i] = Wq[(dout * Dd + din) * Kk + j];
        g_Wk_t[i] = Wk[(dout * Dd + din) * Kk + j];
    } else {
        int i2 = i - nConv;
        if (i2 < Dd * Dd) {
            int e = i2 & (Dd - 1);
            int d = i2 >> 7;
            g_Wv_t[i2] = Wv[e * Dd + d];
            g_Wo_t[i2] = Wo[e * Dd + d];
        }
    }
}

// ---- unified per-thread tile: 4 t-rows x 4 douts (pairs d0,d0+1 / d0+2,d0+3) ----

// Conv chunk: acc[t*2+{0,1}] over this din chunk. All 512 threads participate.
template <int L>
__device__ __forceinline__ void conv_step(ull (&acc)[8], const float* __restrict__ s_in,
                                          const float* __restrict__ s_w,
                                          int t0, int d0, int c0) {
#pragma unroll
    for (int i = 0; i < WCH; i++) {
        int din = c0 + i;
        float x[6];
#pragma unroll
        for (int a = 0; a < 6; a++) {
            int tt = t0 - L + a;
            x[a] = ((unsigned)tt < (unsigned)Tt) ? s_in[tt * XS + din] : 0.f;
        }
        ull xx[6];
#pragma unroll
        for (int a = 0; a < 6; a++) xx[a] = pk2(x[a], x[a]);
#pragma unroll
        for (int j = 0; j < Kk; j++) {
            ulonglong2 w = *(const ulonglong2*)(s_w + (j * WCH + i) * Dd + d0);
#pragma unroll
            for (int t = 0; t < 4; t++) {
                acc[t * 2 + 0] = fma2(w.x, xx[t + j], acc[t * 2 + 0]);
                acc[t * 2 + 1] = fma2(w.y, xx[t + j], acc[t * 2 + 1]);
            }
        }
    }
}

// Dense GEMM chunk: 4t x 4d per thread.
__device__ __forceinline__ void gemm_step(ull (&acc)[8], const float* __restrict__ s_in,
                                          const float* __restrict__ s_w,
                                          int t0, int d0, int c0) {
#pragma unroll
    for (int i = 0; i < WCH; i++) {
        int din = c0 + i;
        ulonglong2 w = *(const ulonglong2*)(s_w + i * Dd + d0);
#pragma unroll
        for (int t = 0; t < 4; t++) {
            float xv = s_in[(t0 + t) * XS + din];
            ull xx = pk2(xv, xv);
            acc[t * 2 + 0] = fma2(w.x, xx, acc[t * 2 + 0]);
            acc[t * 2 + 1] = fma2(w.y, xx, acc[t * 2 + 1]);
        }
    }
}

__device__ __forceinline__ void tile_write(ull (&acc)[8], const float* __restrict__ bias,
                                           float* __restrict__ outp, int out_stride,
                                           int t0, int d0) {
    ull b0 = pk2(bias[d0], bias[d0 + 1]);
    ull b1 = pk2(bias[d0 + 2], bias[d0 + 3]);
#pragma unroll
    for (int t = 0; t < 4; t++) {
        ulonglong2 o;
        o.x = add2(acc[t * 2 + 0], b0);
        o.y = add2(acc[t * 2 + 1], b1);
        *(ulonglong2*)(outp + (t0 + t) * out_stride + d0) = o;
    }
}

// Stage one conv din-chunk (3*16*128 = 6144 floats): 3 float4/thread.
__device__ __forceinline__ void stage_conv(float* s_w, const float* __restrict__ Wt,
                                           int tid, int c0) {
#pragma unroll
    for (int r = 0; r < 3; r++) {
        int f = tid * 4 + r * 2048;
        int j = f >> 11;
        int i = (f >> 7) & 15;
        int dout = f & 127;
        *(float4*)(s_w + f) = *(const float4*)(Wt + (j * Dd + c0 + i) * Dd + dout);
    }
}

// Stage one dense din-chunk (16*128 = 2048 floats): 1 float4/thread.
__device__ __forceinline__ void stage_gemm(float* s_w, const float* __restrict__ Wt,
                                           int tid, int c0) {
    int f = tid * 4;
    int i = f >> 7;
    int dout = f & 127;
    *(float4*)(s_w + f) = *(const float4*)(Wt + (c0 + i) * Dd + dout);
}

__global__ void __launch_bounds__(512)
attn_kernel(const float* __restrict__ query, const float* __restrict__ key,
            const float* __restrict__ value, const int* __restrict__ mask,
            const float* __restrict__ bq, const float* __restrict__ bk,
            const float* __restrict__ bv, const float* __restrict__ bo,
            float* __restrict__ out)
{
    extern __shared__ float sm[];
    float* s_x1 = sm;                        // q input -> q
    float* s_x2 = s_x1 + TILEP;              // k input -> k -> Wo stage
    float* s_x3 = s_x2 + TILEP;              // v input -> v
    float* s_stage = s_x3 + TILEP;           // weight staging -> x buffer
    int*   s_mask = (int*)(s_stage + STAGE_F);

    const int tid = threadIdx.x;
    const int bn = blockIdx.x;
    const int b = bn >> 9;                   // N = 512
    const long long base = (long long)bn * (Tt * Dd);

    const int d0 = (tid & 31) * 4;
    const int t0 = (tid >> 5) * 4;

    // Phase 0: load input tiles (stride 132) + mask
    {
        const float4* gq = (const float4*)(query + base);
        const float4* gk = (const float4*)(key + base);
        const float4* gv = (const float4*)(value + base);
#pragma unroll
        for (int r = 0; r < 4; r++) {
            int idx = tid + r * 512;         // 2048 float4 per tile
            int e = idx * 4;
            int t = e >> 7, d = e & 127;
            int dst = t * XS + d;
            *(float4*)(s_x1 + dst) = gq[idx];
            *(float4*)(s_x2 + dst) = gk[idx];
            *(float4*)(s_x3 + dst) = gv[idx];
        }
        const int* gm = mask + b * (Tt * Tt);
#pragma unroll
        for (int r = 0; r < 8; r++) {
            int m = tid + r * 512;
            s_mask[(m >> 6) * 65 + (m & 63)] = gm[m];
        }
    }

    ull acc[8];

    // Phase 1a: q = causal conv (all threads)
#pragma unroll
    for (int u = 0; u < 8; u++) acc[u] = 0ull;
#pragma unroll 1
    for (int c0 = 0; c0 < Dd; c0 += WCH) {
        __syncthreads();
        stage_conv(s_stage, g_Wq_t, tid, c0);
        __syncthreads();
        conv_step<2>(acc, s_x1, s_stage, t0, d0, c0);
    }
    __syncthreads();
    tile_write(acc, bq, s_x1, XS, t0, d0);

    // Phase 1b: k = same conv
#pragma unroll
    for (int u = 0; u < 8; u++) acc[u] = 0ull;
#pragma unroll 1
    for (int c0 = 0; c0 < Dd; c0 += WCH) {
        __syncthreads();
        stage_conv(s_stage, g_Wk_t, tid, c0);
        __syncthreads();
        conv_step<1>(acc, s_x2, s_stage, t0, d0, c0);
    }
    __syncthreads();
    tile_write(acc, bk, s_x2, XS, t0, d0);

    // Phase 1c: v = dense GEMM
#pragma unroll
    for (int u = 0; u < 8; u++) acc[u] = 0ull;
#pragma unroll 1
    for (int c0 = 0; c0 < Dd; c0 += WCH) {
        __syncthreads();
        stage_gemm(s_stage, g_Wv_t, tid, c0);
        __syncthreads();
        gemm_step(acc, s_x3, s_stage, t0, d0, c0);
    }
    __syncthreads();
    tile_write(acc, bv, s_x3, XS, t0, d0);
    __syncthreads();

    // Phase 2: attention. thread <-> (head h, row t); p[64] in registers.
    {
        const int h = tid >> 6;
        const int t = tid & 63;
        const float* qrow = s_x1 + t * XS + h * DKk;
        const float* kb = s_x2 + h * DKk;
        const float* vb = s_x3 + h * DKk;
        const int* mrow = s_mask + t * 65;

        ull qv[8];
        {
            ulonglong2 a0 = *(const ulonglong2*)(qrow + 0);
            ulonglong2 a1 = *(const ulonglong2*)(qrow + 4);
            ulonglong2 a2 = *(const ulonglong2*)(qrow + 8);
            ulonglong2 a3 = *(const ulonglong2*)(qrow + 12);
            qv[0] = a0.x; qv[1] = a0.y; qv[2] = a1.x; qv[3] = a1.y;
            qv[4] = a2.x; qv[5] = a2.y; qv[6] = a3.x; qv[7] = a3.y;
        }

        float p[64];
        float mx = -3.0e38f;
#pragma unroll
        for (int s = 0; s < 64; s++) {
            const float* kr = kb + s * XS;
            ulonglong2 k0 = *(const ulonglong2*)(kr + 0);
            ulonglong2 k1 = *(const ulonglong2*)(kr + 4);
            ulonglong2 k2 = *(const ulonglong2*)(kr + 8);
            ulonglong2 k3 = *(const ulonglong2*)(kr + 12);
            ull a0 = 0, a1 = 0, a2 = 0, a3 = 0;
            a0 = fma2(qv[0], k0.x, a0);
            a1 = fma2(qv[1], k0.y, a1);
            a2 = fma2(qv[2], k1.x, a2);
            a3 = fma2(qv[3], k1.y, a3);
            a0 = fma2(qv[4], k2.x, a0);
            a1 = fma2(qv[5], k2.y, a1);
            a2 = fma2(qv[6], k3.x, a2);
            a3 = fma2(qv[7], k3.y, a3);
            float2 r0 = upk2(add2(a0, a2));
            float2 r1 = upk2(add2(a1, a3));
            float sc = ((r0.x + r0.y) + (r1.x + r1.y)) * 0.25f;   // 1/sqrt(16)
            sc = (mrow[s] == 0) ? -1.0e9f : sc;
            p[s] = sc;
            mx = fmaxf(mx, sc);
        }

        float sum = 0.f;
#pragma unroll
        for (int s = 0; s < 64; s++) {
            float e = __expf(p[s] - mx);
            p[s] = e;
            sum += e;
        }
        float inv = 1.0f / sum;

        ull xa[8];
#pragma unroll
        for (int u = 0; u < 8; u++) xa[u] = 0ull;
#pragma unroll
        for (int s = 0; s < 64; s++) {
            ull pp = pk2(p[s], p[s]);
            const float* vr = vb + s * XS;
            ulonglong2 v0 = *(const ulonglong2*)(vr + 0);
            ulonglong2 v1 = *(const ulonglong2*)(vr + 4);
            ulonglong2 v2 = *(const ulonglong2*)(vr + 8);
            ulonglong2 v3 = *(const ulonglong2*)(vr + 12);
            xa[0] = fma2(pp, v0.x, xa[0]);
            xa[1] = fma2(pp, v0.y, xa[1]);
            xa[2] = fma2(pp, v1.x, xa[2]);
            xa[3] = fma2(pp, v1.y, xa[3]);
            xa[4] = fma2(pp, v2.x, xa[4]);
            xa[5] = fma2(pp, v2.y, xa[5]);
            xa[6] = fma2(pp, v3.x, xa[6]);
            xa[7] = fma2(pp, v3.y, xa[7]);
        }

        // x row -> s_stage (stride 132)
        float* xrow = s_stage + t * XS + h * DKk;
#pragma unroll
        for (int u = 0; u < 4; u++) {
            float2 lo = upk2(xa[2 * u]);
            float2 hi = upk2(xa[2 * u + 1]);
            *(float4*)(xrow + 4 * u) =
                make_float4(lo.x * inv, lo.y * inv, hi.x * inv, hi.y * inv);
        }
    }

    // Phase 3: output projection (all threads); Wo chunks staged into s_x2.
#pragma unroll
    for (int u = 0; u < 8; u++) acc[u] = 0ull;
#pragma unroll 1
    for (int c0 = 0; c0 < Dd; c0 += WCH) {
        __syncthreads();
        stage_gemm(s_x2, g_Wo_t, tid, c0);
        __syncthreads();
        gemm_step(acc, s_stage, s_x2, t0, d0, c0);
    }
    tile_write(acc, bo, out + base, Dd, t0, d0);
}

extern "C" void kernel_launch(void* const* d_in, const int* in_sizes, int n_in,
                              void* d_out, int out_size) {
    (void)in_sizes; (void)n_in; (void)out_size;
    const float* query = (const float*)d_in[0];
    const float* key   = (const float*)d_in[1];
    const float* value = (const float*)d_in[2];
    const int*   mask  = (const int*)d_in[3];
    const float* Wq = (const float*)d_in[4];
    const float* bq = (const float*)d_in[5];
    const float* Wk = (const float*)d_in[6];
    const float* bk = (const float*)d_in[7];
    const float* Wv = (const float*)d_in[8];
    const float* bv = (const float*)d_in[9];
    const float* Wo = (const float*)d_in[10];
    const float* bo = (const float*)d_in[11];
    float* out = (float*)d_out;

    cudaFuncSetAttribute(attn_kernel, cudaFuncAttributeMaxDynamicSharedMemorySize, SMEM_BYTES);

    prep_kernel<<<256, 256>>>(Wq, Wk, Wv, Wo);
    attn_kernel<<<Bb * Nn, 512, SMEM_BYTES>>>(query, key, value, mask,
                                              bq, bk, bv, bo, out);
}

// round 4
// speedup vs baseline: 1.0011x; 1.0011x over previous
#include <cuda_runtime.h>

// Problem constants
#define Bb 8
#define Nn 512
#define Tt 64
#define Dd 128
#define Hh 8
#define DKk 16
#define Kk 3

#define XS 132                      // padded row stride (floats) for all tiles
#define TILEP (Tt * XS)             // 8448 floats per padded tile
#define WCH 16                      // din chunk
#define STAGE_F TILEP               // stage buffer doubles as x tile (8448 >= 6144)
#define MASK_I (Tt * 65)            // 4160 ints
#define SMEM_FLOATS (3 * TILEP + STAGE_F + MASK_I)   // 37952
#define SMEM_BYTES (SMEM_FLOATS * 4)                 // 151808

typedef unsigned long long ull;

__device__ __forceinline__ ull pk2(float lo, float hi) {
    ull r; asm("mov.b64 %0, {%1,%2};" : "=l"(r) : "f"(lo), "f"(hi)); return r;
}
__device__ __forceinline__ float2 upk2(ull a) {
    float2 f; asm("mov.b64 {%0,%1}, %2;" : "=f"(f.x), "=f"(f.y) : "l"(a)); return f;
}
__device__ __forceinline__ ull fma2(ull a, ull b, ull c) {
    ull d; asm("fma.rn.f32x2 %0, %1, %2, %3;" : "=l"(d) : "l"(a), "l"(b), "l"(c)); return d;
}
__device__ __forceinline__ ull add2(ull a, ull b) {
    ull d; asm("add.rn.f32x2 %0, %1, %2;" : "=l"(d) : "l"(a), "l"(b)); return d;
}

// Pre-transposed weights
__device__ float g_Wq_t[Kk * Dd * Dd];   // [(j*D + din)*D + dout]
__device__ float g_Wk_t[Kk * Dd * Dd];
__device__ float g_Wv_t[Dd * Dd];        // [din*D + e]
__device__ float g_Wo_t[Dd * Dd];

__global__ void prep_kernel(const float* __restrict__ Wq, const float* __restrict__ Wk,
                            const float* __restrict__ Wv, const float* __restrict__ Wo) {
    int i = blockIdx.x * blockDim.x + threadIdx.x;
    const int nConv = Kk * Dd * Dd;  // 49152
    if (i < nConv) {
        int dout = i & (Dd - 1);
        int rem = i >> 7;           // j*D + din
        int din = rem & (Dd - 1);
        int j = rem >> 7;
        g_Wq_t[i] = Wq[(dout * Dd + din) * Kk + j];
        g_Wk_t[i] = Wk[(dout * Dd + din) * Kk + j];
    } else {
        int i2 = i - nConv;
        if (i2 < Dd * Dd) {
            int e = i2 & (Dd - 1);
            int d = i2 >> 7;
            g_Wv_t[i2] = Wv[e * Dd + d];
            g_Wo_t[i2] = Wo[e * Dd + d];
        }
    }
}

// ---- unified per-thread tile: 4 t-rows x 4 douts (pairs d0,d0+1 / d0+2,d0+3) ----

// Conv chunk: acc[t*2+{0,1}] over this din chunk. All 512 threads participate.
template <int L>
__device__ __forceinline__ void conv_step(ull (&acc)[8], const float* __restrict__ s_in,
                                          const float* __restrict__ s_w,
                                          int t0, int d0, int c0) {
#pragma unroll
    for (int i = 0; i < WCH; i++) {
        int din = c0 + i;
        float x[6];
#pragma unroll
        for (int a = 0; a < 6; a++) {
            int tt = t0 - L + a;
            x[a] = ((unsigned)tt < (unsigned)Tt) ? s_in[tt * XS + din] : 0.f;
        }
        ull xx[6];
#pragma unroll
        for (int a = 0; a < 6; a++) xx[a] = pk2(x[a], x[a]);
#pragma unroll
        for (int j = 0; j < Kk; j++) {
            ulonglong2 w = *(const ulonglong2*)(s_w + (j * WCH + i) * Dd + d0);
#pragma unroll
            for (int t = 0; t < 4; t++) {
                acc[t * 2 + 0] = fma2(w.x, xx[t + j], acc[t * 2 + 0]);
                acc[t * 2 + 1] = fma2(w.y, xx[t + j], acc[t * 2 + 1]);
            }
        }
    }
}

// Dense GEMM chunk: 4t x 4d per thread.
__device__ __forceinline__ void gemm_step(ull (&acc)[8], const float* __restrict__ s_in,
                                          const float* __restrict__ s_w,
                                          int t0, int d0, int c0) {
#pragma unroll
    for (int i = 0; i < WCH; i++) {
        int din = c0 + i;
        ulonglong2 w = *(const ulonglong2*)(s_w + i * Dd + d0);
#pragma unroll
        for (int t = 0; t < 4; t++) {
            float xv = s_in[(t0 + t) * XS + din];
            ull xx = pk2(xv, xv);
            acc[t * 2 + 0] = fma2(w.x, xx, acc[t * 2 + 0]);
            acc[t * 2 + 1] = fma2(w.y, xx, acc[t * 2 + 1]);
        }
    }
}

__device__ __forceinline__ void tile_write(ull (&acc)[8], const float* __restrict__ bias,
                                           float* __restrict__ outp, int out_stride,
                                           int t0, int d0) {
    ull b0 = pk2(bias[d0], bias[d0 + 1]);
    ull b1 = pk2(bias[d0 + 2], bias[d0 + 3]);
#pragma unroll
    for (int t = 0; t < 4; t++) {
        ulonglong2 o;
        o.x = add2(acc[t * 2 + 0], b0);
        o.y = add2(acc[t * 2 + 1], b1);
        *(ulonglong2*)(outp + (t0 + t) * out_stride + d0) = o;
    }
}

// Stage one conv din-chunk (3*16*128 = 6144 floats): 3 float4/thread.
__device__ __forceinline__ void stage_conv(float* s_w, const float* __restrict__ Wt,
                                           int tid, int c0) {
#pragma unroll
    for (int r = 0; r < 3; r++) {
        int f = tid * 4 + r * 2048;
        int j = f >> 11;
        int i = (f >> 7) & 15;
        int dout = f & 127;
        *(float4*)(s_w + f) = *(const float4*)(Wt + (j * Dd + c0 + i) * Dd + dout);
    }
}

// Stage one dense din-chunk (16*128 = 2048 floats): 1 float4/thread.
__device__ __forceinline__ void stage_gemm(float* s_w, const float* __restrict__ Wt,
                                           int tid, int c0) {
    int f = tid * 4;
    int i = f >> 7;
    int dout = f & 127;
    *(float4*)(s_w + f) = *(const float4*)(Wt + (c0 + i) * Dd + dout);
}

__global__ void __launch_bounds__(512)
attn_kernel(const float* __restrict__ query, const float* __restrict__ key,
            const float* __restrict__ value, const int* __restrict__ mask,
            const float* __restrict__ bq, const float* __restrict__ bk,
            const float* __restrict__ bv, const float* __restrict__ bo,
            float* __restrict__ out)
{
    extern __shared__ float sm[];
    float* s_x1 = sm;                        // q input -> q
    float* s_x2 = s_x1 + TILEP;              // k input -> k -> Wo stage
    float* s_x3 = s_x2 + TILEP;              // v input -> v
    float* s_stage = s_x3 + TILEP;           // weight staging -> x buffer
    int*   s_mask = (int*)(s_stage + STAGE_F);

    const int tid = threadIdx.x;
    const int bn = blockIdx.x;
    const int b = bn >> 9;                   // N = 512
    const long long base = (long long)bn * (Tt * Dd);

    const int d0 = (tid & 31) * 4;
    const int t0 = (tid >> 5) * 4;

    // Phase 0: load input tiles (stride 132) + mask
    {
        const float4* gq = (const float4*)(query + base);
        const float4* gk = (const float4*)(key + base);
        const float4* gv = (const float4*)(value + base);
#pragma unroll
        for (int r = 0; r < 4; r++) {
            int idx = tid + r * 512;         // 2048 float4 per tile
            int e = idx * 4;
            int t = e >> 7, d = e & 127;
            int dst = t * XS + d;
            *(float4*)(s_x1 + dst) = gq[idx];
            *(float4*)(s_x2 + dst) = gk[idx];
            *(float4*)(s_x3 + dst) = gv[idx];
        }
        const int* gm = mask + b * (Tt * Tt);
#pragma unroll
        for (int r = 0; r < 8; r++) {
            int m = tid + r * 512;
            s_mask[(m >> 6) * 65 + (m & 63)] = gm[m];
        }
    }

    ull acc[8];

    // Phase 1a: q = causal conv (all threads)
#pragma unroll
    for (int u = 0; u < 8; u++) acc[u] = 0ull;
#pragma unroll 1
    for (int c0 = 0; c0 < Dd; c0 += WCH) {
        __syncthreads();
        stage_conv(s_stage, g_Wq_t, tid, c0);
        __syncthreads();
        conv_step<2>(acc, s_x1, s_stage, t0, d0, c0);
    }
    __syncthreads();
    tile_write(acc, bq, s_x1, XS, t0, d0);

    // Phase 1b: k = same conv
#pragma unroll
    for (int u = 0; u < 8; u++) acc[u] = 0ull;
#pragma unroll 1
    for (int c0 = 0; c0 < Dd; c0 += WCH) {
        __syncthreads();
        stage_conv(s_stage, g_Wk_t, tid, c0);
        __syncthreads();
        conv_step<1>(acc, s_x2, s_stage, t0, d0, c0);
    }
    __syncthreads();
    tile_write(acc, bk, s_x2, XS, t0, d0);

    // Phase 1c: v = dense GEMM
#pragma unroll
    for (int u = 0; u < 8; u++) acc[u] = 0ull;
#pragma unroll 1
    for (int c0 = 0; c0 < Dd; c0 += WCH) {
        __syncthreads();
        stage_gemm(s_stage, g_Wv_t, tid, c0);
        __syncthreads();
        gemm_step(acc, s_x3, s_stage, t0, d0, c0);
    }
    __syncthreads();
    tile_write(acc, bv, s_x3, XS, t0, d0);
    __syncthreads();

    // Phase 2: attention. thread <-> (head h, row t); p[64] in registers.
    {
        const int h = tid >> 6;
        const int t = tid & 63;
        const float* qrow = s_x1 + t * XS + h * DKk;
        const float* kb = s_x2 + h * DKk;
        const float* vb = s_x3 + h * DKk;
        const int* mrow = s_mask + t * 65;

        ull qv[8];
        {
            ulonglong2 a0 = *(const ulonglong2*)(qrow + 0);
            ulonglong2 a1 = *(const ulonglong2*)(qrow + 4);
            ulonglong2 a2 = *(const ulonglong2*)(qrow + 8);
            ulonglong2 a3 = *(const ulonglong2*)(qrow + 12);
            qv[0] = a0.x; qv[1] = a0.y; qv[2] = a1.x; qv[3] = a1.y;
            qv[4] = a2.x; qv[5] = a2.y; qv[6] = a3.x; qv[7] = a3.y;
        }

        float p[64];
        float mx = -3.0e38f;
#pragma unroll
        for (int s = 0; s < 64; s++) {
            const float* kr = kb + s * XS;
            ulonglong2 k0 = *(const ulonglong2*)(kr + 0);
            ulonglong2 k1 = *(const ulonglong2*)(kr + 4);
            ulonglong2 k2 = *(const ulonglong2*)(kr + 8);
            ulonglong2 k3 = *(const ulonglong2*)(kr + 12);
            ull a0 = 0, a1 = 0, a2 = 0, a3 = 0;
            a0 = fma2(qv[0], k0.x, a0);
            a1 = fma2(qv[1], k0.y, a1);
            a2 = fma2(qv[2], k1.x, a2);
            a3 = fma2(qv[3], k1.y, a3);
            a0 = fma2(qv[4], k2.x, a0);
            a1 = fma2(qv[5], k2.y, a1);
            a2 = fma2(qv[6], k3.x, a2);
            a3 = fma2(qv[7], k3.y, a3);
            float2 r0 = upk2(add2(a0, a2));
            float2 r1 = upk2(add2(a1, a3));
            float sc = ((r0.x + r0.y) + (r1.x + r1.y)) * 0.25f;   // 1/sqrt(16)
            sc = (mrow[s] == 0) ? -1.0e9f : sc;
            p[s] = sc;
            mx = fmaxf(mx, sc);
        }

        float sum = 0.f;
#pragma unroll
        for (int s = 0; s < 64; s++) {
            float e = __expf(p[s] - mx);
            p[s] = e;
            sum += e;
        }
        float inv = 1.0f / sum;

        ull xa[8];
#pragma unroll
        for (int u = 0; u < 8; u++) xa[u] = 0ull;
#pragma unroll
        for (int s = 0; s < 64; s++) {
            ull pp = pk2(p[s], p[s]);
            const float* vr = vb + s * XS;
            ulonglong2 v0 = *(const ulonglong2*)(vr + 0);
            ulonglong2 v1 = *(const ulonglong2*)(vr + 4);
            ulonglong2 v2 = *(const ulonglong2*)(vr + 8);
            ulonglong2 v3 = *(const ulonglong2*)(vr + 12);
            xa[0] = fma2(pp, v0.x, xa[0]);
            xa[1] = fma2(pp, v0.y, xa[1]);
            xa[2] = fma2(pp, v1.x, xa[2]);
            xa[3] = fma2(pp, v1.y, xa[3]);
            xa[4] = fma2(pp, v2.x, xa[4]);
            xa[5] = fma2(pp, v2.y, xa[5]);
            xa[6] = fma2(pp, v3.x, xa[6]);
            xa[7] = fma2(pp, v3.y, xa[7]);
        }

        // x row -> s_stage (stride 132)
        float* xrow = s_stage + t * XS + h * DKk;
#pragma unroll
        for (int u = 0; u < 4; u++) {
            float2 lo = upk2(xa[2 * u]);
            float2 hi = upk2(xa[2 * u + 1]);
            *(float4*)(xrow + 4 * u) =
                make_float4(lo.x * inv, lo.y * inv, hi.x * inv, hi.y * inv);
        }
    }

    // Phase 3: output projection (all threads); Wo chunks staged into s_x2.
#pragma unroll
    for (int u = 0; u < 8; u++) acc[u] = 0ull;
#pragma unroll 1
    for (int c0 = 0; c0 < Dd; c0 += WCH) {
        __syncthreads();
        stage_gemm(s_x2, g_Wo_t, tid, c0);
        __syncthreads();
        gemm_step(acc, s_stage, s_x2, t0, d0, c0);
    }
    tile_write(acc, bo, out + base, Dd, t0, d0);
}

extern "C" void kernel_launch(void* const* d_in, const int* in_sizes, int n_in,
                              void* d_out, int out_size) {
    (void)in_sizes; (void)n_in; (void)out_size;
    const float* query = (const float*)d_in[0];
    const float* key   = (const float*)d_in[1];
    const float* value = (const float*)d_in[2];
    const int*   mask  = (const int*)d_in[3];
    const float* Wq = (const float*)d_in[4];
    const float* bq = (const float*)d_in[5];
    const float* Wk = (const float*)d_in[6];
    const float* bk = (const float*)d_in[7];
    const float* Wv = (const float*)d_in[8];
    const float* bv = (const float*)d_in[9];
    const float* Wo = (const float*)d_in[10];
    const float* bo = (const float*)d_in[11];
    float* out = (float*)d_out;

    cudaFuncSetAttribute(attn_kernel, cudaFuncAttributeMaxDynamicSharedMemorySize, SMEM_BYTES);

    prep_kernel<<<256, 256>>>(Wq, Wk, Wv, Wo);
    attn_kernel<<<Bb * Nn, 512, SMEM_BYTES>>>(query, key, value, mask,
                                              bq, bk, bv, bo, out);
}

// round 6
// speedup vs baseline: 1.9273x; 1.9252x over previous
#include <cuda_runtime.h>
#include <cstdint>

// Problem: B=8, N=512, T=64, D=128, H=8, DK=16, K=3
// One (b,n) tile per CTA. 512 threads = 16 warps (4 m-tiles x 4 n-groups).

// smem layout (float offsets)
#define S_IN 0                    // 68 rows x 132 (rows 0,1,66,67 = zero pad)
#define S_B  8976                 // 16384 floats: B fragments for one j-chunk
#define S_Q  25360                // 64 x 132 result tile
#define S_K  33808
#define S_V  42256
#define SMEM_FLOATS 50704
#define SMEM_BYTES (SMEM_FLOATS * 4)   // 202816

// packed-weight sections (float offsets into g_pack)
#define PQ 0
#define PK 49152
#define PV 98304
#define PO 114688

typedef unsigned long long ull;

__device__ float g_pack[131072];

// ---------------- PTX helpers ----------------
__device__ __forceinline__ uint32_t smem_u32(const void* p) {
    uint32_t a;
    asm("{ .reg .u64 t; cvta.to.shared.u64 t, %1; cvt.u32.u64 %0, t; }" : "=r"(a) : "l"(p));
    return a;
}
__device__ __forceinline__ uint32_t rnd_tf32(float f) {
    uint32_t r; asm("cvt.rna.tf32.f32 %0, %1;" : "=r"(r) : "f"(f)); return r;
}
__device__ __forceinline__ ull pk2(float lo, float hi) {
    ull r; asm("mov.b64 %0, {%1,%2};" : "=l"(r) : "f"(lo), "f"(hi)); return r;
}
__device__ __forceinline__ float2 upk2(ull a) {
    float2 f; asm("mov.b64 {%0,%1}, %2;" : "=f"(f.x), "=f"(f.y) : "l"(a)); return f;
}
__device__ __forceinline__ ull fma2(ull a, ull b, ull c) {
    ull d; asm("fma.rn.f32x2 %0, %1, %2, %3;" : "=l"(d) : "l"(a), "l"(b), "l"(c)); return d;
}
__device__ __forceinline__ ull add2(ull a, ull b) {
    ull d; asm("add.rn.f32x2 %0, %1, %2;" : "=l"(d) : "l"(a), "l"(b)); return d;
}
__device__ __forceinline__ uint4 lds128(uint32_t a) {
    uint4 v;
    asm volatile("ld.shared.v4.b32 {%0,%1,%2,%3}, [%4];"
                 : "=r"(v.x), "=r"(v.y), "=r"(v.z), "=r"(v.w) : "r"(a));
    return v;
}
// tf32 A-fragment gather: ldmatrix.b16 on 16B rows of 4 tf32 values
__device__ __forceinline__ void ldsm4(uint32_t (&r)[4], uint32_t a) {
    asm volatile("ldmatrix.sync.aligned.m8n8.x4.shared.b16 {%0,%1,%2,%3}, [%4];"
                 : "=r"(r[0]), "=r"(r[1]), "=r"(r[2]), "=r"(r[3]) : "r"(a));
}
__device__ __forceinline__ void mma8(float (&c)[4], const uint32_t (&a)[4],
                                     uint32_t b0, uint32_t b1) {
    asm volatile(
        "mma.sync.aligned.m16n8k8.row.col.f32.tf32.tf32.f32 "
        "{%0,%1,%2,%3},{%4,%5,%6,%7},{%8,%9},{%0,%1,%2,%3};"
        : "+f"(c[0]), "+f"(c[1]), "+f"(c[2]), "+f"(c[3])
        : "r"(a[0]), "r"(a[1]), "r"(a[2]), "r"(a[3]), "r"(b0), "r"(b1));
}

// ---------------- prep: pack weights into B-fragment order, tf32-rounded ----------
// layout per section: l = ((j*8 + ksp)*16 + nj)*32 + lane, 4 floats each:
//   b0(k=2ksp),b1(k=2ksp),b0(k=2ksp+1),b1(k=2ksp+1); n = nj*8 + lane>>2
__global__ void prep_kernel(const float* __restrict__ Wq, const float* __restrict__ Wk,
                            const float* __restrict__ Wv, const float* __restrict__ Wo) {
    int idx = blockIdx.x * blockDim.x + threadIdx.x;
    if (idx >= 32768) return;
    const float* W; float* dst; int l, conv;
    if (idx < 12288)      { l = idx;         W = Wq; dst = g_pack + PQ + l * 4; conv = 1; }
    else if (idx < 24576) { l = idx - 12288; W = Wk; dst = g_pack + PK + l * 4; conv = 1; }
    else if (idx < 28672) { l = idx - 24576; W = Wv; dst = g_pack + PV + l * 4; conv = 0; }
    else                  { l = idx - 28672; W = Wo; dst = g_pack + PO + l * 4; conv = 0; }
    int lane = l & 31, nj = (l >> 5) & 15, ksp = (l >> 9) & 7;
    int j = conv ? (l >> 12) : 0;
    int n = nj * 8 + (lane >> 2);
    int c = lane & 3;
    int d0 = ksp * 16 + c;      // kstep 2ksp
    int d1 = d0 + 8;            // kstep 2ksp+1
    float4 o;
    if (conv) {
        o.x = W[(n * 128 + d0) * 3 + j];
        o.y = W[(n * 128 + d0 + 4) * 3 + j];
        o.z = W[(n * 128 + d1) * 3 + j];
        o.w = W[(n * 128 + d1 + 4) * 3 + j];
    } else {
        o.x = W[n * 128 + d0];
        o.y = W[n * 128 + d0 + 4];
        o.z = W[n * 128 + d1];
        o.w = W[n * 128 + d1 + 4];
    }
    uint4 r;
    r.x = rnd_tf32(o.x); r.y = rnd_tf32(o.y);
    r.z = rnd_tf32(o.z); r.w = rnd_tf32(o.w);
    *(uint4*)dst = r;
}

// ---------------- device-side building blocks ----------------
__device__ __forceinline__ void load_input(float* sm, const float* __restrict__ g, int tid) {
#pragma unroll
    for (int r = 0; r < 4; r++) {
        int idx = tid + r * 512;                 // 2048 float4
        float4 f = *(const float4*)(g + idx * 4);
        uint4 v;
        v.x = rnd_tf32(f.x); v.y = rnd_tf32(f.y);
        v.z = rnd_tf32(f.z); v.w = rnd_tf32(f.w);
        int t = idx >> 5, d = (idx & 31) * 4;
        *(uint4*)(sm + S_IN + (t + 2) * 132 + d) = v;
    }
}
__device__ __forceinline__ void stage_B(float* sm, const float* __restrict__ g, int tid) {
#pragma unroll
    for (int r = 0; r < 8; r++) {
        int idx = tid + r * 512;                 // 4096 float4
        *(float4*)(sm + S_B + idx * 4) = *(const float4*)(g + idx * 4);
    }
}
__device__ __forceinline__ void mma_chunk(float (&acc)[4][4], uint32_t a_base, uint32_t b_base) {
#pragma unroll
    for (int ksp = 0; ksp < 8; ksp++) {
        uint32_t A0[4], A1[4];
        ldsm4(A0, a_base);
        ldsm4(A1, a_base + 32);
        uint4 B0 = lds128(b_base);
        uint4 B1 = lds128(b_base + 512);
        uint4 B2 = lds128(b_base + 1024);
        uint4 B3 = lds128(b_base + 1536);
        mma8(acc[0], A0, B0.x, B0.y); mma8(acc[0], A1, B0.z, B0.w);
        mma8(acc[1], A0, B1.x, B1.y); mma8(acc[1], A1, B1.z, B1.w);
        mma8(acc[2], A0, B2.x, B2.y); mma8(acc[2], A1, B2.z, B2.w);
        mma8(acc[3], A0, B3.x, B3.y); mma8(acc[3], A1, B3.z, B3.w);
        a_base += 64;        // 2 ksteps = 16 floats
        b_base += 8192;      // next ksp block
    }
}
__device__ __forceinline__ void zacc(float (&acc)[4][4]) {
#pragma unroll
    for (int i = 0; i < 4; i++)
#pragma unroll
        for (int k = 0; k < 4; k++) acc[i][k] = 0.f;
}
__device__ __forceinline__ void epi_s(float* dst, const float* __restrict__ bias,
                                      float (&acc)[4][4], int lane, int m0, int ncol0) {
    int r0 = m0 + (lane >> 2), r1 = r0 + 8, cb = (lane & 3) * 2;
#pragma unroll
    for (int nj = 0; nj < 4; nj++) {
        int col = ncol0 + nj * 8 + cb;
        float2 bb = *(const float2*)(bias + col);
        *(float2*)(dst + r0 * 132 + col) = make_float2(acc[nj][0] + bb.x, acc[nj][1] + bb.y);
        *(float2*)(dst + r1 * 132 + col) = make_float2(acc[nj][2] + bb.x, acc[nj][3] + bb.y);
    }
}
__device__ __forceinline__ void epi_g(float* dst, const float* __restrict__ bias,
                                      float (&acc)[4][4], int lane, int m0, int ncol0) {
    int r0 = m0 + (lane >> 2), r1 = r0 + 8, cb = (lane & 3) * 2;
#pragma unroll
    for (int nj = 0; nj < 4; nj++) {
        int col = ncol0 + nj * 8 + cb;
        float2 bb = *(const float2*)(bias + col);
        *(float2*)(dst + r0 * 128 + col) = make_float2(acc[nj][0] + bb.x, acc[nj][1] + bb.y);
        *(float2*)(dst + r1 * 128 + col) = make_float2(acc[nj][2] + bb.x, acc[nj][3] + bb.y);
    }
}

__global__ void __launch_bounds__(512, 1)
attn_kernel(const float* __restrict__ query, const float* __restrict__ key,
            const float* __restrict__ value, const int* __restrict__ mask,
            const float* __restrict__ bq, const float* __restrict__ bk,
            const float* __restrict__ bv, const float* __restrict__ bo,
            float* __restrict__ out)
{
    extern __shared__ float sm[];
    uint32_t smb = smem_u32(sm);
    const int tid = threadIdx.x, lane = tid & 31, wid = tid >> 5;
    const int cta = blockIdx.x, b = cta >> 9;
    const long long base = (long long)cta * 8192;

    const int m0 = (wid >> 2) * 16;
    const int njg = wid & 3;
    const int ncol0 = njg * 32;
    const int arow = (lane & 7) + ((lane >> 3) & 1) * 8 + m0;
    const int acolb = (lane >> 4) * 4;
    const uint32_t a_thr = smb + (uint32_t)((S_IN + arow * 132 + acolb) * 4);
    const uint32_t b_thr = smb + (uint32_t)(S_B * 4) + (uint32_t)((njg * 4 * 32 + lane) * 16);

    // zero-pad rows 0,1,66,67 of s_in
    if (tid < 528) {
        int r = tid / 132, c = tid - r * 132;
        sm[S_IN + ((r < 2) ? r : (64 + r)) * 132 + c] = 0.f;
    }

    float acc[4][4];

    // ---- q = causal conv (jshift = j) ----
    load_input(sm, query + base, tid);
    zacc(acc);
#pragma unroll 1
    for (int j = 0; j < 3; j++) {
        stage_B(sm, g_pack + PQ + j * 16384, tid);
        __syncthreads();
        mma_chunk(acc, a_thr + j * 528, b_thr);
        __syncthreads();
    }
    epi_s(sm + S_Q, bq, acc, lane, m0, ncol0);

    // ---- k = same conv (jshift = j+1) ----
    load_input(sm, key + base, tid);
    zacc(acc);
#pragma unroll 1
    for (int j = 0; j < 3; j++) {
        stage_B(sm, g_pack + PK + j * 16384, tid);
        __syncthreads();
        mma_chunk(acc, a_thr + (j + 1) * 528, b_thr);
        __syncthreads();
    }
    epi_s(sm + S_K, bk, acc, lane, m0, ncol0);

    // ---- v = dense GEMM (jshift = 2) ----
    load_input(sm, value + base, tid);
    zacc(acc);
    stage_B(sm, g_pack + PV, tid);
    __syncthreads();
    mma_chunk(acc, a_thr + 2 * 528, b_thr);
    __syncthreads();
    epi_s(sm + S_V, bv, acc, lane, m0, ncol0);
    __syncthreads();

    // ---- attention: fp32 FFMA2 SIMT, thread <-> (head h, row t) ----
    {
        const int h = tid >> 6, t = tid & 63;
        const float* qrow = sm + S_Q + t * 132 + h * 16;
        const float* kb = sm + S_K + h * 16;
        const float* vb = sm + S_V + h * 16;
        unsigned mb0 = 0, mb1 = 0;
        const int4* mr = (const int4*)(mask + b * 4096 + t * 64);
#pragma unroll
        for (int u = 0; u < 16; u++) {
            int4 m = mr[u];
            unsigned bits = (unsigned)(m.x != 0) | ((unsigned)(m.y != 0) << 1) |
                            ((unsigned)(m.z != 0) << 2) | ((unsigned)(m.w != 0) << 3);
            if (u < 8) mb0 |= bits << (u * 4);
            else       mb1 |= bits << ((u - 8) * 4);
        }

        ull qv[8];
        {
            ulonglong2 a0 = *(const ulonglong2*)(qrow + 0);
            ulonglong2 a1 = *(const ulonglong2*)(qrow + 4);
            ulonglong2 a2 = *(const ulonglong2*)(qrow + 8);
            ulonglong2 a3 = *(const ulonglong2*)(qrow + 12);
            qv[0] = a0.x; qv[1] = a0.y; qv[2] = a1.x; qv[3] = a1.y;
            qv[4] = a2.x; qv[5] = a2.y; qv[6] = a3.x; qv[7] = a3.y;
        }

        float p[64];
        float mx = -3.0e38f;
#pragma unroll
        for (int s = 0; s < 64; s++) {
            const float* kr = kb + s * 132;
            ulonglong2 k0 = *(const ulonglong2*)(kr + 0);
            ulonglong2 k1 = *(const ulonglong2*)(kr + 4);
            ulonglong2 k2 = *(const ulonglong2*)(kr + 8);
            ulonglong2 k3 = *(const ulonglong2*)(kr + 12);
            ull a0 = fma2(qv[0], k0.x, 0ull), a1 = fma2(qv[1], k0.y, 0ull);
            ull a2 = fma2(qv[2], k1.x, 0ull), a3 = fma2(qv[3], k1.y, 0ull);
            a0 = fma2(qv[4], k2.x, a0); a1 = fma2(qv[5], k2.y, a1);
            a2 = fma2(qv[6], k3.x, a2); a3 = fma2(qv[7], k3.y, a3);
            float2 r0 = upk2(add2(a0, a2));
            float2 r1 = upk2(add2(a1, a3));
            float sc = ((r0.x + r0.y) + (r1.x + r1.y)) * 0.25f;   // 1/sqrt(16)
            unsigned live = (s < 32) ? ((mb0 >> s) & 1u) : ((mb1 >> (s - 32)) & 1u);
            sc = live ? sc : -1.0e9f;
            p[s] = sc;
            mx = fmaxf(mx, sc);
        }
        float sum = 0.f;
#pragma unroll
        for (int s = 0; s < 64; s++) {
            float e = __expf(p[s] - mx);
            p[s] = e;
            sum += e;
        }
        float inv = 1.0f / sum;

        ull xa[8];
#pragma unroll
        for (int u = 0; u < 8; u++) xa[u] = 0ull;
#pragma unroll
        for (int s = 0; s < 64; s++) {
            ull pp = pk2(p[s], p[s]);
            const float* vr = vb + s * 132;
            ulonglong2 v0 = *(const ulonglong2*)(vr + 0);
            ulonglong2 v1 = *(const ulonglong2*)(vr + 4);
            ulonglong2 v2 = *(const ulonglong2*)(vr + 8);
            ulonglong2 v3 = *(const ulonglong2*)(vr + 12);
            xa[0] = fma2(pp, v0.x, xa[0]); xa[1] = fma2(pp, v0.y, xa[1]);
            xa[2] = fma2(pp, v1.x, xa[2]); xa[3] = fma2(pp, v1.y, xa[3]);
            xa[4] = fma2(pp, v2.x, xa[4]); xa[5] = fma2(pp, v2.y, xa[5]);
            xa[6] = fma2(pp, v3.x, xa[6]); xa[7] = fma2(pp, v3.y, xa[7]);
        }

        // x -> s_in rows t+2 (tf32-rounded, feeds O-proj MMA)
        float* xr = sm + S_IN + (t + 2) * 132 + h * 16;
#pragma unroll
        for (int u = 0; u < 4; u++) {
            float2 lo = upk2(xa[2 * u]);
            float2 hi = upk2(xa[2 * u + 1]);
            uint4 v;
            v.x = rnd_tf32(lo.x * inv); v.y = rnd_tf32(lo.y * inv);
            v.z = rnd_tf32(hi.x * inv); v.w = rnd_tf32(hi.y * inv);
            *(uint4*)(xr + 4 * u) = v;
        }
    }
    __syncthreads();

    // ---- output projection (jshift = 2), epilogue straight to gmem ----
    zacc(acc);
    stage_B(sm, g_pack + PO, tid);
    __syncthreads();
    mma_chunk(acc, a_thr + 2 * 528, b_thr);
    epi_g(out + base, bo, acc, lane, m0, ncol0);
}

extern "C" void kernel_launch(void* const* d_in, const int* in_sizes, int n_in,
                              void* d_out, int out_size) {
    (void)in_sizes; (void)n_in; (void)out_size;
    const float* query = (const float*)d_in[0];
    const float* key   = (const float*)d_in[1];
    const float* value = (const float*)d_in[2];
    const int*   mask  = (const int*)d_in[3];
    const float* Wq = (const float*)d_in[4];
    const float* bq = (const float*)d_in[5];
    const float* Wk = (const float*)d_in[6];
    const float* bk = (const float*)d_in[7];
    const float* Wv = (const float*)d_in[8];
    const float* bv = (const float*)d_in[9];
    const float* Wo = (const float*)d_in[10];
    const float* bo = (const float*)d_in[11];
    float* out = (float*)d_out;

    cudaFuncSetAttribute(attn_kernel, cudaFuncAttributeMaxDynamicSharedMemorySize, SMEM_BYTES);
    prep_kernel<<<128, 256>>>(Wq, Wk, Wv, Wo);
    attn_kernel<<<4096, 512, SMEM_BYTES>>>(query, key, value, mask, bq, bk, bv, bo, out);
}

// round 7
// speedup vs baseline: 2.3371x; 1.2127x over previous
#include <cuda_runtime.h>
#include <cstdint>

// B=8, N=512, T=64, D=128, H=8, DK=16, K=3. One (b,n) tile per CTA, 512 thr.

// smem float offsets
#define S_IN  0          // 68 x 132 input tile (rows 0,1,66,67 zero)
#define S_B   8976       // 16384: weight-fragment stage; overlaid by KPH/KPL after k GEMM
#define KPH   8976       // 8192: packed kT hi (B-frag order)
#define KPL   17168      // 8192: packed kT lo
#define S_QH  25360      // 64 x 132 q hi tile
#define S_QL  33808      // 64 x 132 q lo tile
#define S_VP  42256      // 8192: packed V (B-frag order)
#define S_MSK 50448      // 64 ull row masks
#define SMEM_FLOATS 50576
#define SMEM_BYTES (SMEM_FLOATS * 4)   // 202304

// packed-weight sections (float offsets into g_pack)
#define PQ 0
#define PK 49152
#define PV 98304
#define PO 114688

typedef unsigned long long ull;
__device__ float g_pack[131072];

// ---------------- PTX helpers ----------------
__device__ __forceinline__ uint32_t smem_u32(const void* p) {
    uint32_t a;
    asm("{ .reg .u64 t; cvta.to.shared.u64 t, %1; cvt.u32.u64 %0, t; }" : "=r"(a) : "l"(p));
    return a;
}
__device__ __forceinline__ uint32_t rnd_tf32(float f) {
    uint32_t r; asm("cvt.rna.tf32.f32 %0, %1;" : "=r"(r) : "f"(f)); return r;
}
__device__ __forceinline__ uint4 lds128(uint32_t a) {
    uint4 v;
    asm volatile("ld.shared.v4.b32 {%0,%1,%2,%3}, [%4];"
                 : "=r"(v.x), "=r"(v.y), "=r"(v.z), "=r"(v.w) : "r"(a));
    return v;
}
__device__ __forceinline__ void ldsm4(uint32_t (&r)[4], uint32_t a) {
    asm volatile("ldmatrix.sync.aligned.m8n8.x4.shared.b16 {%0,%1,%2,%3}, [%4];"
                 : "=r"(r[0]), "=r"(r[1]), "=r"(r[2]), "=r"(r[3]) : "r"(a));
}
__device__ __forceinline__ void mma8(float (&c)[4], const uint32_t (&a)[4],
                                     uint32_t b0, uint32_t b1) {
    asm volatile(
        "mma.sync.aligned.m16n8k8.row.col.f32.tf32.tf32.f32 "
        "{%0,%1,%2,%3},{%4,%5,%6,%7},{%8,%9},{%0,%1,%2,%3};"
        : "+f"(c[0]), "+f"(c[1]), "+f"(c[2]), "+f"(c[3])
        : "r"(a[0]), "r"(a[1]), "r"(a[2]), "r"(a[3]), "r"(b0), "r"(b1));
}

// ---------------- prep: pack weights into B-fragment order, tf32-rounded -------
// l = ((j*8 + ksp)*16 + nj)*32 + lane; float4 = {b0_k0,b1_k0,b0_k1,b1_k1}
__global__ void prep_kernel(const float* __restrict__ Wq, const float* __restrict__ Wk,
                            const float* __restrict__ Wv, const float* __restrict__ Wo) {
    int idx = blockIdx.x * blockDim.x + threadIdx.x;
    if (idx >= 32768) return;
    const float* W; float* dst; int l, conv; float scale = 1.0f;
    if (idx < 12288)      { l = idx;         W = Wq; dst = g_pack + PQ + l * 4; conv = 1; scale = 0.25f; }
    else if (idx < 24576) { l = idx - 12288; W = Wk; dst = g_pack + PK + l * 4; conv = 1; }
    else if (idx < 28672) { l = idx - 24576; W = Wv; dst = g_pack + PV + l * 4; conv = 0; }
    else                  { l = idx - 28672; W = Wo; dst = g_pack + PO + l * 4; conv = 0; }
    int lane = l & 31, nj = (l >> 5) & 15, ksp = (l >> 9) & 7;
    int j = conv ? (l >> 12) : 0;
    int n = nj * 8 + (lane >> 2);
    int c = lane & 3;
    int d0 = ksp * 16 + c, d1 = d0 + 8;
    float4 o;
    if (conv) {
        o.x = W[(n * 128 + d0) * 3 + j];
        o.y = W[(n * 128 + d0 + 4) * 3 + j];
        o.z = W[(n * 128 + d1) * 3 + j];
        o.w = W[(n * 128 + d1 + 4) * 3 + j];
    } else {
        o.x = W[n * 128 + d0];
        o.y = W[n * 128 + d0 + 4];
        o.z = W[n * 128 + d1];
        o.w = W[n * 128 + d1 + 4];
    }
    uint4 r;
    r.x = rnd_tf32(o.x * scale); r.y = rnd_tf32(o.y * scale);
    r.z = rnd_tf32(o.z * scale); r.w = rnd_tf32(o.w * scale);
    *(uint4*)dst = r;
}

// ---------------- building blocks ----------------
__device__ __forceinline__ void load_input(float* sm, const float* __restrict__ g, int tid) {
#pragma unroll
    for (int r = 0; r < 4; r++) {
        int idx = tid + r * 512;
        float4 f = *(const float4*)(g + idx * 4);
        uint4 v;
        v.x = rnd_tf32(f.x); v.y = rnd_tf32(f.y);
        v.z = rnd_tf32(f.z); v.w = rnd_tf32(f.w);
        int t = idx >> 5, d = (idx & 31) * 4;
        *(uint4*)(sm + S_IN + (t + 2) * 132 + d) = v;
    }
}
__device__ __forceinline__ void stage_B(float* sm, const float* __restrict__ g, int tid) {
#pragma unroll
    for (int r = 0; r < 8; r++) {
        int idx = tid + r * 512;
        *(float4*)(sm + S_B + idx * 4) = *(const float4*)(g + idx * 4);
    }
}
__device__ __forceinline__ void mma_chunk(float (&acc)[4][4], uint32_t a_base, uint32_t b_base) {
#pragma unroll
    for (int ksp = 0; ksp < 8; ksp++) {
        uint32_t A0[4], A1[4];
        ldsm4(A0, a_base);
        ldsm4(A1, a_base + 32);
        uint4 B0 = lds128(b_base);
        uint4 B1 = lds128(b_base + 512);
        uint4 B2 = lds128(b_base + 1024);
        uint4 B3 = lds128(b_base + 1536);
        mma8(acc[0], A0, B0.x, B0.y); mma8(acc[0], A1, B0.z, B0.w);
        mma8(acc[1], A0, B1.x, B1.y); mma8(acc[1], A1, B1.z, B1.w);
        mma8(acc[2], A0, B2.x, B2.y); mma8(acc[2], A1, B2.z, B2.w);
        mma8(acc[3], A0, B3.x, B3.y); mma8(acc[3], A1, B3.z, B3.w);
        a_base += 64;
        b_base += 8192;
    }
}
__device__ __forceinline__ void zacc(float (&acc)[4][4]) {
#pragma unroll
    for (int i = 0; i < 4; i++)
#pragma unroll
        for (int k = 0; k < 4; k++) acc[i][k] = 0.f;
}
// q epilogue: hi/lo tiles (bias*0.25 since Wq pre-scaled)
__device__ __forceinline__ void epi_q(float* sm, const float* __restrict__ bq,
                                      float (&acc)[4][4], int lane, int m0, int ncol0) {
    int r0 = m0 + (lane >> 2), r1 = r0 + 8, cb = (lane & 3) * 2;
#pragma unroll
    for (int nj = 0; nj < 4; nj++) {
        int col = ncol0 + nj * 8 + cb;
        float2 bb = *(const float2*)(bq + col);
        float v0 = acc[nj][0] + bb.x * 0.25f, v1 = acc[nj][1] + bb.y * 0.25f;
        float v2 = acc[nj][2] + bb.x * 0.25f, v3 = acc[nj][3] + bb.y * 0.25f;
        uint32_t h0 = rnd_tf32(v0), h1 = rnd_tf32(v1), h2 = rnd_tf32(v2), h3 = rnd_tf32(v3);
        float l0 = v0 - __uint_as_float(h0), l1 = v1 - __uint_as_float(h1);
        float l2 = v2 - __uint_as_float(h2), l3 = v3 - __uint_as_float(h3);
        *(float2*)(sm + S_QH + r0 * 132 + col) = make_float2(__uint_as_float(h0), __uint_as_float(h1));
        *(float2*)(sm + S_QH + r1 * 132 + col) = make_float2(__uint_as_float(h2), __uint_as_float(h3));
        *(float2*)(sm + S_QL + r0 * 132 + col) = make_float2(__uint_as_float(rnd_tf32(l0)), __uint_as_float(rnd_tf32(l1)));
        *(float2*)(sm + S_QL + r1 * 132 + col) = make_float2(__uint_as_float(rnd_tf32(l2)), __uint_as_float(rnd_tf32(l3)));
    }
}
// k epilogue: packed kT (B-frag order), hi+lo
__device__ __forceinline__ void epi_k(float* sm, const float* __restrict__ bk,
                                      float (&acc)[4][4], int lane, int m0, int ncol0) {
    int r0 = m0 + (lane >> 2), cb = (lane & 3) * 2;
#pragma unroll
    for (int nj = 0; nj < 4; nj++) {
        int col0 = ncol0 + nj * 8 + cb;
        float2 bb = *(const float2*)(bk + col0);
#pragma unroll
        for (int p = 0; p < 2; p++) {
            int col = col0 + p;
            int h = col >> 4, dk = col & 15;
            float bv = p ? bb.y : bb.x;
#pragma unroll
            for (int rr = 0; rr < 2; rr++) {
                int s = r0 + rr * 8;
                float val = acc[nj][rr * 2 + p] + bv;
                uint32_t hi = rnd_tf32(val);
                float lo = val - __uint_as_float(hi);
                int fl = ((h * 8 + (s >> 3)) * 32 + (s & 7) * 4 + (dk & 3)) * 4 + (dk >> 2);
                sm[KPH + fl] = __uint_as_float(hi);
                sm[KPL + fl] = __uint_as_float(rnd_tf32(lo));
            }
        }
    }
}
// v epilogue: packed V (B-frag order for PV)
__device__ __forceinline__ void epi_v(float* sm, const float* __restrict__ bv,
                                      float (&acc)[4][4], int lane, int m0, int ncol0) {
    int r0 = m0 + (lane >> 2), cb = (lane & 3) * 2;
#pragma unroll
    for (int nj = 0; nj < 4; nj++) {
        int col0 = ncol0 + nj * 8 + cb;
        float2 bb = *(const float2*)(bv + col0);
#pragma unroll
        for (int p = 0; p < 2; p++) {
            int col = col0 + p;
            int h = col >> 4, dk = col & 15;
            float bvv = p ? bb.y : bb.x;
#pragma unroll
            for (int rr = 0; rr < 2; rr++) {
                int s = r0 + rr * 8;
                float val = acc[nj][rr * 2 + p] + bvv;
                int fl = (((h * 4 + (s >> 4)) * 2 + (dk >> 3)) * 32
                          + (dk & 7) * 4 + (s & 3)) * 4 + ((s >> 2) & 3);
                sm[S_VP + fl] = __uint_as_float(rnd_tf32(val));
            }
        }
    }
}
__device__ __forceinline__ void epi_g(float* dst, const float* __restrict__ bias,
                                      float (&acc)[4][4], int lane, int m0, int ncol0) {
    int r0 = m0 + (lane >> 2), r1 = r0 + 8, cb = (lane & 3) * 2;
#pragma unroll
    for (int nj = 0; nj < 4; nj++) {
        int col = ncol0 + nj * 8 + cb;
        float2 bb = *(const float2*)(bias + col);
        *(float2*)(dst + r0 * 128 + col) = make_float2(acc[nj][0] + bb.x, acc[nj][1] + bb.y);
        *(float2*)(dst + r1 * 128 + col) = make_float2(acc[nj][2] + bb.x, acc[nj][3] + bb.y);
    }
}
// acc-layout -> A-frag-layout via quad shuffles (p = exp'd scores of one 8-col block)
__device__ __forceinline__ void build_afrag(uint32_t (&A)[4], const float (&p)[4], int lane) {
    int c = lane & 3;
    int q0 = (lane & ~3) | (c >> 1);
    int q1 = q0 + 2;
    bool odd = c & 1;
    float x0 = __shfl_sync(0xffffffffu, p[0], q0);
    float x1 = __shfl_sync(0xffffffffu, p[1], q0);
    A[0] = rnd_tf32(odd ? x1 : x0);
    float y0 = __shfl_sync(0xffffffffu, p[2], q0);
    float y1 = __shfl_sync(0xffffffffu, p[3], q0);
    A[1] = rnd_tf32(odd ? y1 : y0);
    float z0 = __shfl_sync(0xffffffffu, p[0], q1);
    float z1 = __shfl_sync(0xffffffffu, p[1], q1);
    A[2] = rnd_tf32(odd ? z1 : z0);
    float w0 = __shfl_sync(0xffffffffu, p[2], q1);
    float w1 = __shfl_sync(0xffffffffu, p[3], q1);
    A[3] = rnd_tf32(odd ? w1 : w0);
}

__global__ void __launch_bounds__(512, 1)
attn_kernel(const float* __restrict__ query, const float* __restrict__ key,
            const float* __restrict__ value, const int* __restrict__ mask,
            const float* __restrict__ bq, const float* __restrict__ bk,
            const float* __restrict__ bv, const float* __restrict__ bo,
            float* __restrict__ out)
{
    extern __shared__ float sm[];
    uint32_t smb = smem_u32(sm);
    const int tid = threadIdx.x, lane = tid & 31, wid = tid >> 5;
    const int cta = blockIdx.x, b = cta >> 9;
    const long long base = (long long)cta * 8192;

    const int m0 = (wid >> 2) * 16;
    const int njg = wid & 3;
    const int ncol0 = njg * 32;
    const int arow = (lane & 7) + ((lane >> 3) & 1) * 8 + m0;
    const int acolb = (lane >> 4) * 4;
    const uint32_t a_thr = smb + (uint32_t)((S_IN + arow * 132 + acolb) * 4);
    const uint32_t b_thr = smb + (uint32_t)(S_B * 4) + (uint32_t)((njg * 4 * 32 + lane) * 16);

    // zero-pad rows 0,1,66,67 of S_IN
    if (tid < 528) {
        int r = tid / 132, c = tid - r * 132;
        sm[S_IN + ((r < 2) ? r : (64 + r)) * 132 + c] = 0.f;
    }
    // row bitmasks -> smem
    if (tid < 64) {
        ull m = 0;
        const int4* mr = (const int4*)(mask + b * 4096 + tid * 64);
#pragma unroll
        for (int u = 0; u < 16; u++) {
            int4 mm = mr[u];
            ull bits = (ull)(mm.x != 0) | ((ull)(mm.y != 0) << 1) |
                       ((ull)(mm.z != 0) << 2) | ((ull)(mm.w != 0) << 3);
            m |= bits << (u * 4);
        }
        ((ull*)(sm + S_MSK))[tid] = m;
    }

    float acc[4][4];

    // ---- v = dense GEMM (jshift=2) -> packed VP ----
    load_input(sm, value + base, tid);
    stage_B(sm, g_pack + PV, tid);
    __syncthreads();
    zacc(acc);
    mma_chunk(acc, a_thr + 2 * 528, b_thr);
    __syncthreads();
    epi_v(sm, bv, acc, lane, m0, ncol0);

    // ---- q = causal conv -> hi/lo tiles ----
    load_input(sm, query + base, tid);
    zacc(acc);
#pragma unroll 1
    for (int j = 0; j < 3; j++) {
        stage_B(sm, g_pack + PQ + j * 16384, tid);
        __syncthreads();
        mma_chunk(acc, a_thr + j * 528, b_thr);
        __syncthreads();
    }
    epi_q(sm, bq, acc, lane, m0, ncol0);

    // ---- k = same conv -> packed kT hi/lo (overlays S_B) ----
    load_input(sm, key + base, tid);
    zacc(acc);
#pragma unroll 1
    for (int j = 0; j < 3; j++) {
        stage_B(sm, g_pack + PK + j * 16384, tid);
        __syncthreads();
        mma_chunk(acc, a_thr + (j + 1) * 528, b_thr);
        __syncthreads();
    }
    epi_k(sm, bk, acc, lane, m0, ncol0);
    __syncthreads();

    // ---- attention via mma.sync: warp w -> head w>>1, row-half (w&1)*32 ----
    {
        const int h = wid >> 1;
        const int mh = (wid & 1) * 32;
        const int r = lane >> 2, c = lane & 3;
        const int row_l = (lane & 7) + ((lane >> 3) & 1) * 8;
        const int coloff = h * 16 + (lane >> 4) * 4;

        float pa[2][8][4];
#pragma unroll
        for (int mt = 0; mt < 2; mt++)
#pragma unroll
            for (int nt = 0; nt < 8; nt++)
#pragma unroll
                for (int i = 0; i < 4; i++) pa[mt][nt][i] = 0.f;

        // QK^T, split-tf32 (hh + hl + lh)
#pragma unroll
        for (int mt = 0; mt < 2; mt++) {
            uint32_t aH = smb + (uint32_t)((S_QH + (mh + mt * 16 + row_l) * 132 + coloff) * 4);
            uint32_t aL = smb + (uint32_t)((S_QL + (mh + mt * 16 + row_l) * 132 + coloff) * 4);
            uint32_t AH0[4], AH1[4], AL0[4], AL1[4];
            ldsm4(AH0, aH); ldsm4(AH1, aH + 32);
            ldsm4(AL0, aL); ldsm4(AL1, aL + 32);
#pragma unroll
            for (int nt = 0; nt < 8; nt++) {
                uint4 BH = lds128(smb + (uint32_t)(KPH * 4) + (uint32_t)(((h * 8 + nt) * 32 + lane) * 16));
                uint4 BL = lds128(smb + (uint32_t)(KPL * 4) + (uint32_t)(((h * 8 + nt) * 32 + lane) * 16));
                mma8(pa[mt][nt], AH0, BH.x, BH.y); mma8(pa[mt][nt], AH1, BH.z, BH.w);
                mma8(pa[mt][nt], AH0, BL.x, BL.y); mma8(pa[mt][nt], AH1, BL.z, BL.w);
                mma8(pa[mt][nt], AL0, BH.x, BH.y); mma8(pa[mt][nt], AL1, BH.z, BH.w);
            }
        }

        // masked softmax on fragments (rows rA=mh+mt*16+r, rB=rA+8)
        float inv[2][2];
#pragma unroll
        for (int mt = 0; mt < 2; mt++) {
            ull mA = ((const ull*)(sm + S_MSK))[mh + mt * 16 + r];
            ull mB = ((const ull*)(sm + S_MSK))[mh + mt * 16 + r + 8];
            float mxA = -3.0e38f, mxB = -3.0e38f;
#pragma unroll
            for (int nt = 0; nt < 8; nt++) {
                int c0 = nt * 8 + 2 * c, c1 = c0 + 1;
                float v;
                v = ((mA >> c0) & 1) ? pa[mt][nt][0] : -1.0e9f; pa[mt][nt][0] = v; mxA = fmaxf(mxA, v);
                v = ((mA >> c1) & 1) ? pa[mt][nt][1] : -1.0e9f; pa[mt][nt][1] = v; mxA = fmaxf(mxA, v);
                v = ((mB >> c0) & 1) ? pa[mt][nt][2] : -1.0e9f; pa[mt][nt][2] = v; mxB = fmaxf(mxB, v);
                v = ((mB >> c1) & 1) ? pa[mt][nt][3] : -1.0e9f; pa[mt][nt][3] = v; mxB = fmaxf(mxB, v);
            }
            mxA = fmaxf(mxA, __shfl_xor_sync(0xffffffffu, mxA, 1));
            mxA = fmaxf(mxA, __shfl_xor_sync(0xffffffffu, mxA, 2));
            mxB = fmaxf(mxB, __shfl_xor_sync(0xffffffffu, mxB, 1));
            mxB = fmaxf(mxB, __shfl_xor_sync(0xffffffffu, mxB, 2));
            float sA = 0.f, sB = 0.f;
#pragma unroll
            for (int nt = 0; nt < 8; nt++) {
                float e;
                e = __expf(pa[mt][nt][0] - mxA); pa[mt][nt][0] = e; sA += e;
                e = __expf(pa[mt][nt][1] - mxA); pa[mt][nt][1] = e; sA += e;
                e = __expf(pa[mt][nt][2] - mxB); pa[mt][nt][2] = e; sB += e;
                e = __expf(pa[mt][nt][3] - mxB); pa[mt][nt][3] = e; sB += e;
            }
            sA += __shfl_xor_sync(0xffffffffu, sA, 1);
            sA += __shfl_xor_sync(0xffffffffu, sA, 2);
            sB += __shfl_xor_sync(0xffffffffu, sB, 1);
            sB += __shfl_xor_sync(0xffffffffu, sB, 2);
            inv[mt][0] = 1.0f / sA;
            inv[mt][1] = 1.0f / sB;
        }

        // P @ V (plain tf32; P re-laid acc->A-frag via shuffles)
        float xacc[2][2][4];
#pragma unroll
        for (int mt = 0; mt < 2; mt++)
#pragma unroll
            for (int n2 = 0; n2 < 2; n2++)
#pragma unroll
                for (int i = 0; i < 4; i++) xacc[mt][n2][i] = 0.f;
#pragma unroll
        for (int mt = 0; mt < 2; mt++) {
#pragma unroll
            for (int kp = 0; kp < 4; kp++) {
                uint32_t A0[4], A1[4];
                build_afrag(A0, pa[mt][2 * kp], lane);
                build_afrag(A1, pa[mt][2 * kp + 1], lane);
                uint4 V0 = lds128(smb + (uint32_t)(S_VP * 4) + (uint32_t)((((h * 4 + kp) * 2 + 0) * 32 + lane) * 16));
                uint4 V1 = lds128(smb + (uint32_t)(S_VP * 4) + (uint32_t)((((h * 4 + kp) * 2 + 1) * 32 + lane) * 16));
                mma8(xacc[mt][0], A0, V0.x, V0.y); mma8(xacc[mt][0], A1, V0.z, V0.w);
                mma8(xacc[mt][1], A0, V1.x, V1.y); mma8(xacc[mt][1], A1, V1.z, V1.w);
            }
        }

        // x -> S_IN rows t+2 (tf32-rounded, feeds O-proj)
#pragma unroll
        for (int mt = 0; mt < 2; mt++) {
            int rA = mh + mt * 16 + r, rB = rA + 8;
#pragma unroll
            for (int n2 = 0; n2 < 2; n2++) {
                int col = h * 16 + n2 * 8 + 2 * c;
                float iA = inv[mt][0], iB = inv[mt][1];
                *(float2*)(sm + S_IN + (2 + rA) * 132 + col) =
                    make_float2(__uint_as_float(rnd_tf32(xacc[mt][n2][0] * iA)),
                                __uint_as_float(rnd_tf32(xacc[mt][n2][1] * iA)));
                *(float2*)(sm + S_IN + (2 + rB) * 132 + col) =
                    make_float2(__uint_as_float(rnd_tf32(xacc[mt][n2][2] * iB)),
                                __uint_as_float(rnd_tf32(xacc[mt][n2][3] * iB)));
            }
        }
    }
    __syncthreads();

    // ---- output projection (jshift=2), epilogue to gmem ----
    stage_B(sm, g_pack + PO, tid);
    __syncthreads();
    zacc(acc);
    mma_chunk(acc, a_thr + 2 * 528, b_thr);
    epi_g(out + base, bo, acc, lane, m0, ncol0);
}

extern "C" void kernel_launch(void* const* d_in, const int* in_sizes, int n_in,
                              void* d_out, int out_size) {
    (void)in_sizes; (void)n_in; (void)out_size;
    const float* query = (const float*)d_in[0];
    const float* key   = (const float*)d_in[1];
    const float* value = (const float*)d_in[2];
    const int*   mask  = (const int*)d_in[3];
    const float* Wq = (const float*)d_in[4];
    const float* bq = (const float*)d_in[5];
    const float* Wk = (const float*)d_in[6];
    const float* bk = (const float*)d_in[7];
    const float* Wv = (const float*)d_in[8];
    const float* bv = (const float*)d_in[9];
    const float* Wo = (const float*)d_in[10];
    const float* bo = (const float*)d_in[11];
    float* out = (float*)d_out;

    cudaFuncSetAttribute(attn_kernel, cudaFuncAttributeMaxDynamicSharedMemorySize, SMEM_BYTES);
    prep_kernel<<<128, 256>>>(Wq, Wk, Wv, Wo);
    attn_kernel<<<4096, 512, SMEM_BYTES>>>(query, key, value, mask, bq, bk, bv, bo, out);
}

// round 8
// speedup vs baseline: 4.2697x; 1.8269x over previous
#include <cuda_runtime.h>
#include <cuda_fp16.h>
#include <cstdint>

// B=8, N=512, T=64, D=128, H=8, DK=16, K=3. One (b,n) tile per CTA, 512 thr = 16 warps.
// All operands fp16 (11-bit significand == tf32), fp32 accumulate.

// byte offsets in dynamic smem
#define S_IN_B   0          // 68 rows x 136 fp16, 272B/row (rows 0,1,66,67 zero pad)
#define S_ST_B   18496      // 32KB: one K=128 chunk of packed B fragments
#define S_QP_B   51264      // 64 x 136 fp16 q tile (ldmatrix-able)
#define S_KP_B   68672      // 16KB packed K^T B-frags (per head)
#define S_VP_B   85056      // 16KB packed V B-frags (per head)
#define S_MSK_B  101440     // 64 x ull row masks
#define SMEM_BYTES 101952

// g_pack chunk offsets (uint32 units; each chunk = 8192 uint32 = 32KB)
#define PQ4 0
#define PK4 24576
#define PV4 49152
#define PO4 57344

typedef unsigned long long ull;
__device__ uint32_t g_pack[65536];

// ---------------- PTX helpers ----------------
__device__ __forceinline__ uint32_t smem_u32(const void* p) {
    uint32_t a;
    asm("{ .reg .u64 t; cvta.to.shared.u64 t, %1; cvt.u32.u64 %0, t; }" : "=r"(a) : "l"(p));
    return a;
}
// pack two fp32 -> fp16x2 (lo -> low half, hi -> high half), RN
__device__ __forceinline__ uint32_t h2(float lo, float hi) {
    uint32_t r; asm("cvt.rn.f16x2.f32 %0, %1, %2;" : "=r"(r) : "f"(hi), "f"(lo)); return r;
}
__device__ __forceinline__ uint4 lds128(uint32_t a) {
    uint4 v;
    asm volatile("ld.shared.v4.b32 {%0,%1,%2,%3}, [%4];"
                 : "=r"(v.x), "=r"(v.y), "=r"(v.z), "=r"(v.w) : "r"(a));
    return v;
}
__device__ __forceinline__ void ldsm4(uint32_t (&r)[4], uint32_t a) {
    asm volatile("ldmatrix.sync.aligned.m8n8.x4.shared.b16 {%0,%1,%2,%3}, [%4];"
                 : "=r"(r[0]), "=r"(r[1]), "=r"(r[2]), "=r"(r[3]) : "r"(a));
}
__device__ __forceinline__ void mma16(float (&c)[4], const uint32_t (&a)[4],
                                      uint32_t b0, uint32_t b1) {
    asm volatile(
        "mma.sync.aligned.m16n8k16.row.col.f32.f16.f16.f32 "
        "{%0,%1,%2,%3},{%4,%5,%6,%7},{%8,%9},{%0,%1,%2,%3};"
        : "+f"(c[0]), "+f"(c[1]), "+f"(c[2]), "+f"(c[3])
        : "r"(a[0]), "r"(a[1]), "r"(a[2]), "r"(a[3]), "r"(b0), "r"(b1));
}

// ---------------- prep: pack weights as fp16 B-fragments ----------------
// chunk = K=128 slice: uint4 index (ksp*8 + njp)*32 + lane
// uint4 = {frag(2njp).r0, frag(2njp).r1, frag(2njp+1).r0, frag(2njp+1).r1}
// frag(nj).r0 lane l = {W[n][k0], W[n][k0+1]}, n = nj*8 + (l>>2), k0 = ksp*16 + 2(l&3); r1: k0+8
__global__ void prep_kernel(const float* __restrict__ Wq, const float* __restrict__ Wk,
                            const float* __restrict__ Wv, const float* __restrict__ Wo) {
    int idx = blockIdx.x * blockDim.x + threadIdx.x;   // 16384
    if (idx >= 16384) return;
    const float* W; int base4, within, j = 0, conv; float sc = 1.0f;
    if (idx < 6144)       { W = Wq; j = idx >> 11; within = idx & 2047; base4 = PQ4 / 4 + idx; conv = 1; sc = 0.25f; }
    else if (idx < 12288) { int i2 = idx - 6144; W = Wk; j = i2 >> 11; within = i2 & 2047; base4 = PK4 / 4 + i2; conv = 1; }
    else if (idx < 14336) { int i2 = idx - 12288; W = Wv; within = i2; base4 = PV4 / 4 + i2; conv = 0; }
    else                  { int i2 = idx - 14336; W = Wo; within = i2; base4 = PO4 / 4 + i2; conv = 0; }
    int lane = within & 31, njp = (within >> 5) & 7, ksp = within >> 8;
    int n0 = njp * 16 + (lane >> 2);
    int n1 = n0 + 8;
    int k0 = ksp * 16 + 2 * (lane & 3);
    float w[8];
    if (conv) {
        w[0] = W[(n0 * 128 + k0) * 3 + j];     w[1] = W[(n0 * 128 + k0 + 1) * 3 + j];
        w[2] = W[(n0 * 128 + k0 + 8) * 3 + j]; w[3] = W[(n0 * 128 + k0 + 9) * 3 + j];
        w[4] = W[(n1 * 128 + k0) * 3 + j];     w[5] = W[(n1 * 128 + k0 + 1) * 3 + j];
        w[6] = W[(n1 * 128 + k0 + 8) * 3 + j]; w[7] = W[(n1 * 128 + k0 + 9) * 3 + j];
    } else {
        w[0] = W[n0 * 128 + k0];     w[1] = W[n0 * 128 + k0 + 1];
        w[2] = W[n0 * 128 + k0 + 8]; w[3] = W[n0 * 128 + k0 + 9];
        w[4] = W[n1 * 128 + k0];     w[5] = W[n1 * 128 + k0 + 1];
        w[6] = W[n1 * 128 + k0 + 8]; w[7] = W[n1 * 128 + k0 + 9];
    }
    uint4 o;
    o.x = h2(w[0] * sc, w[1] * sc);
    o.y = h2(w[2] * sc, w[3] * sc);
    o.z = h2(w[4] * sc, w[5] * sc);
    o.w = h2(w[6] * sc, w[7] * sc);
    ((uint4*)g_pack)[base4] = o;
}

// ---------------- building blocks ----------------
__device__ __forceinline__ void load_input(char* smc, const float* __restrict__ g, int tid) {
#pragma unroll
    for (int r = 0; r < 4; r++) {
        int idx = tid + r * 512;                       // 2048 float4
        float4 f = *(const float4*)(g + idx * 4);
        int t = idx >> 5, d = (idx & 31) * 4;
        uint2 v;
        v.x = h2(f.x, f.y);
        v.y = h2(f.z, f.w);
        *(uint2*)(smc + S_IN_B + (t + 2) * 272 + d * 2) = v;
    }
}
__device__ __forceinline__ void stage_B(char* smc, const uint4* __restrict__ g4, int tid) {
#pragma unroll
    for (int r = 0; r < 4; r++) {
        int idx = tid + r * 512;                       // 2048 uint4
        *(uint4*)(smc + S_ST_B + idx * 16) = g4[idx];
    }
}
// one K=128 chunk: 8 k16-steps, warp tile 16x32
__device__ __forceinline__ void mma_chunk(float (&acc)[4][4], uint32_t a0, uint32_t b0) {
#pragma unroll
    for (int ksp = 0; ksp < 8; ksp++) {
        uint32_t A[4];
        ldsm4(A, a0 + ksp * 32);
        uint4 B01 = lds128(b0 + ksp * 4096);
        uint4 B23 = lds128(b0 + ksp * 4096 + 512);
        mma16(acc[0], A, B01.x, B01.y);
        mma16(acc[1], A, B01.z, B01.w);
        mma16(acc[2], A, B23.x, B23.y);
        mma16(acc[3], A, B23.z, B23.w);
    }
}
__device__ __forceinline__ void zacc(float (&acc)[4][4]) {
#pragma unroll
    for (int i = 0; i < 4; i++)
#pragma unroll
        for (int k = 0; k < 4; k++) acc[i][k] = 0.f;
}
__device__ __forceinline__ void epi_q(char* smc, const float* __restrict__ bq,
                                      float (&acc)[4][4], int lane, int m0, int ncol0) {
    int r0 = m0 + (lane >> 2), cb = (lane & 3) * 2;
#pragma unroll
    for (int nj = 0; nj < 4; nj++) {
        int col = ncol0 + nj * 8 + cb;
        float2 bb = *(const float2*)(bq + col);
        *(uint32_t*)(smc + S_QP_B + r0 * 272 + col * 2) =
            h2(acc[nj][0] + bb.x * 0.25f, acc[nj][1] + bb.y * 0.25f);
        *(uint32_t*)(smc + S_QP_B + (r0 + 8) * 272 + col * 2) =
            h2(acc[nj][2] + bb.x * 0.25f, acc[nj][3] + bb.y * 0.25f);
    }
}
__device__ __forceinline__ void epi_k(char* smc, const float* __restrict__ bk,
                                      float (&acc)[4][4], int lane, int m0, int ncol0) {
#pragma unroll
    for (int nj = 0; nj < 4; nj++) {
#pragma unroll
        for (int i = 0; i < 4; i++) {
            int s = m0 + (lane >> 2) + (i >> 1) * 8;
            int col = ncol0 + nj * 8 + (lane & 3) * 2 + (i & 1);
            int h = col >> 4, dk = col & 15;
            int nt = s >> 3, ntp = nt >> 1;
            int lp = ((s & 7) << 2) | ((dk >> 1) & 3);
            int off = ((h * 4 + ntp) * 32 + lp) * 16 + (nt & 1) * 8 + (dk >> 3) * 4 + (dk & 1) * 2;
            *(__half*)(smc + S_KP_B + off) = __float2half_rn(acc[nj][i] + __ldg(bk + col));
        }
    }
}
__device__ __forceinline__ void epi_v(char* smc, const float* __restrict__ bv,
                                      float (&acc)[4][4], int lane, int m0, int ncol0) {
#pragma unroll
    for (int nj = 0; nj < 4; nj++) {
#pragma unroll
        for (int i = 0; i < 4; i++) {
            int s = m0 + (lane >> 2) + (i >> 1) * 8;
            int col = ncol0 + nj * 8 + (lane & 3) * 2 + (i & 1);
            int h = col >> 4, dk = col & 15;
            int ksp = s >> 4, nt = dk >> 3;
            int lp = ((dk & 7) << 2) | ((s >> 1) & 3);
            int off = ((h * 4 + ksp) * 32 + lp) * 16 + nt * 8 + ((s >> 3) & 1) * 4 + (s & 1) * 2;
            *(__half*)(smc + S_VP_B + off) = __float2half_rn(acc[nj][i] + __ldg(bv + col));
        }
    }
}
__device__ __forceinline__ void epi_g(float* __restrict__ dst, const float* __restrict__ bias,
                                      float (&acc)[4][4], int lane, int m0, int ncol0) {
    int r0 = m0 + (lane >> 2), r1 = r0 + 8, cb = (lane & 3) * 2;
#pragma unroll
    for (int nj = 0; nj < 4; nj++) {
        int col = ncol0 + nj * 8 + cb;
        float2 bb = *(const float2*)(bias + col);
        *(float2*)(dst + r0 * 128 + col) = make_float2(acc[nj][0] + bb.x, acc[nj][1] + bb.y);
        *(float2*)(dst + r1 * 128 + col) = make_float2(acc[nj][2] + bb.x, acc[nj][3] + bb.y);
    }
}

__global__ void __launch_bounds__(512, 1)
attn_kernel(const float* __restrict__ query, const float* __restrict__ key,
            const float* __restrict__ value, const int* __restrict__ mask,
            const float* __restrict__ bq, const float* __restrict__ bk,
            const float* __restrict__ bv, const float* __restrict__ bo,
            float* __restrict__ out)
{
    extern __shared__ char smc[];
    uint32_t smb = smem_u32(smc);
    const int tid = threadIdx.x, lane = tid & 31, wid = tid >> 5;
    const int cta = blockIdx.x, b = cta >> 9;
    const long long base = (long long)cta * 8192;

    const int m0 = (wid >> 2) * 16;
    const int njg = wid & 3;
    const int ncol0 = njg * 32;
    // A-frag thread address pieces
    const uint32_t a_row_off = (uint32_t)((m0 + (lane & 15)) * 272 + (lane >> 4) * 16);
    const uint32_t b_thr = smb + S_ST_B + (uint32_t)(((njg * 2) * 32 + lane) * 16);

    // zero pad rows 0,1,66,67 (68 words per row)
    if (tid < 272) {
        int rr = tid / 68, off = tid - rr * 68;
        int row = (rr < 2) ? rr : (64 + rr);
        *(uint32_t*)(smc + S_IN_B + row * 272 + off * 4) = 0u;
    }
    // row bitmasks
    if (tid < 64) {
        ull m = 0;
        const int4* mr = (const int4*)(mask + b * 4096 + tid * 64);
#pragma unroll
        for (int u = 0; u < 16; u++) {
            int4 mm = mr[u];
            ull bits = (ull)(mm.x != 0) | ((ull)(mm.y != 0) << 1) |
                       ((ull)(mm.z != 0) << 2) | ((ull)(mm.w != 0) << 3);
            m |= bits << (u * 4);
        }
        *(ull*)(smc + S_MSK_B + tid * 8) = m;
    }

    float acc[4][4];

    // ---- v = dense GEMM (rows t+2) -> packed VP ----
    load_input(smc, value + base, tid);
    stage_B(smc, (const uint4*)(g_pack + PV4), tid);
    __syncthreads();
    zacc(acc);
    mma_chunk(acc, smb + S_IN_B + 2 * 272 + a_row_off, b_thr);
    __syncthreads();
    epi_v(smc, bv, acc, lane, m0, ncol0);

    // ---- q = causal conv (rows t+j) -> QP fp16 tile ----
    load_input(smc, query + base, tid);
    stage_B(smc, (const uint4*)(g_pack + PQ4), tid);
    __syncthreads();
    zacc(acc);
#pragma unroll 1
    for (int j = 0; j < 3; j++) {
        mma_chunk(acc, smb + S_IN_B + j * 272 + a_row_off, b_thr);
        __syncthreads();
        if (j < 2) {
            stage_B(smc, (const uint4*)(g_pack + PQ4 + (j + 1) * 8192), tid);
            __syncthreads();
        }
    }
    epi_q(smc, bq, acc, lane, m0, ncol0);

    // ---- k = same conv (rows t+j+1) -> packed KP ----
    load_input(smc, key + base, tid);
    stage_B(smc, (const uint4*)(g_pack + PK4), tid);
    __syncthreads();
    zacc(acc);
#pragma unroll 1
    for (int j = 0; j < 3; j++) {
        mma_chunk(acc, smb + S_IN_B + (j + 1) * 272 + a_row_off, b_thr);
        __syncthreads();
        if (j < 2) {
            stage_B(smc, (const uint4*)(g_pack + PK4 + (j + 1) * 8192), tid);
            __syncthreads();
        }
    }
    epi_k(smc, bk, acc, lane, m0, ncol0);
    // stage Wo now (S_ST free; attention doesn't touch it)
    stage_B(smc, (const uint4*)(g_pack + PO4), tid);
    __syncthreads();

    // ---- attention: warp w -> head w>>1, rows (w&1)*32 .. +31 ----
    {
        const int h = wid >> 1;
        const int mh = (wid & 1) * 32;
        const int r = lane >> 2, c = lane & 3;

        float pa[2][8][4];
#pragma unroll
        for (int mt = 0; mt < 2; mt++)
#pragma unroll
            for (int nt = 0; nt < 8; nt++)
#pragma unroll
                for (int i = 0; i < 4; i++) pa[mt][nt][i] = 0.f;

        // QK^T (fp16 single pass)
#pragma unroll
        for (int mt = 0; mt < 2; mt++) {
            uint32_t A[4];
            ldsm4(A, smb + S_QP_B + (mh + mt * 16 + (lane & 15)) * 272
                     + h * 32 + (lane >> 4) * 16);
#pragma unroll
            for (int ntp = 0; ntp < 4; ntp++) {
                uint4 Bf = lds128(smb + S_KP_B + (uint32_t)(((h * 4 + ntp) * 32 + lane) * 16));
                mma16(pa[mt][2 * ntp], A, Bf.x, Bf.y);
                mma16(pa[mt][2 * ntp + 1], A, Bf.z, Bf.w);
            }
        }

        // masked softmax on fragments
        float inv[2][2];
#pragma unroll
        for (int mt = 0; mt < 2; mt++) {
            ull mA = *(const ull*)(smc + S_MSK_B + (mh + mt * 16 + r) * 8);
            ull mB = *(const ull*)(smc + S_MSK_B + (mh + mt * 16 + r + 8) * 8);
            float mxA = -3.0e38f, mxB = -3.0e38f;
#pragma unroll
            for (int nt = 0; nt < 8; nt++) {
                int c0 = nt * 8 + 2 * c, c1 = c0 + 1;
                float v;
                v = ((mA >> c0) & 1) ? pa[mt][nt][0] : -1.0e9f; pa[mt][nt][0] = v; mxA = fmaxf(mxA, v);
                v = ((mA >> c1) & 1) ? pa[mt][nt][1] : -1.0e9f; pa[mt][nt][1] = v; mxA = fmaxf(mxA, v);
                v = ((mB >> c0) & 1) ? pa[mt][nt][2] : -1.0e9f; pa[mt][nt][2] = v; mxB = fmaxf(mxB, v);
                v = ((mB >> c1) & 1) ? pa[mt][nt][3] : -1.0e9f; pa[mt][nt][3] = v; mxB = fmaxf(mxB, v);
            }
            mxA = fmaxf(mxA, __shfl_xor_sync(0xffffffffu, mxA, 1));
            mxA = fmaxf(mxA, __shfl_xor_sync(0xffffffffu, mxA, 2));
            mxB = fmaxf(mxB, __shfl_xor_sync(0xffffffffu, mxB, 1));
            mxB = fmaxf(mxB, __shfl_xor_sync(0xffffffffu, mxB, 2));
            float sA = 0.f, sB = 0.f;
#pragma unroll
            for (int nt = 0; nt < 8; nt++) {
                float e;
                e = __expf(pa[mt][nt][0] - mxA); pa[mt][nt][0] = e; sA += e;
                e = __expf(pa[mt][nt][1] - mxA); pa[mt][nt][1] = e; sA += e;
                e = __expf(pa[mt][nt][2] - mxB); pa[mt][nt][2] = e; sB += e;
                e = __expf(pa[mt][nt][3] - mxB); pa[mt][nt][3] = e; sB += e;
            }
            sA += __shfl_xor_sync(0xffffffffu, sA, 1);
            sA += __shfl_xor_sync(0xffffffffu, sA, 2);
            sB += __shfl_xor_sync(0xffffffffu, sB, 1);
            sB += __shfl_xor_sync(0xffffffffu, sB, 2);
            inv[mt][0] = 1.0f / sA;
            inv[mt][1] = 1.0f / sB;
        }

        // P @ V (P -> fp16 A-frags, same-lane packing; no shuffles)
        float xacc[2][2][4];
#pragma unroll
        for (int mt = 0; mt < 2; mt++)
#pragma unroll
            for (int n2 = 0; n2 < 2; n2++)
#pragma unroll
                for (int i = 0; i < 4; i++) xacc[mt][n2][i] = 0.f;
#pragma unroll
        for (int mt = 0; mt < 2; mt++) {
#pragma unroll
            for (int kp = 0; kp < 4; kp++) {
                uint32_t A[4];
                A[0] = h2(pa[mt][2 * kp][0], pa[mt][2 * kp][1]);
                A[1] = h2(pa[mt][2 * kp][2], pa[mt][2 * kp][3]);
                A[2] = h2(pa[mt][2 * kp + 1][0], pa[mt][2 * kp + 1][1]);
                A[3] = h2(pa[mt][2 * kp + 1][2], pa[mt][2 * kp + 1][3]);
                uint4 V = lds128(smb + S_VP_B + (uint32_t)(((h * 4 + kp) * 32 + lane) * 16));
                mma16(xacc[mt][0], A, V.x, V.y);
                mma16(xacc[mt][1], A, V.z, V.w);
            }
        }

        // x (normalized, fp16) -> S_IN rows t+2, feeds O-proj
#pragma unroll
        for (int mt = 0; mt < 2; mt++) {
            int rA = mh + mt * 16 + r, rB = rA + 8;
            float iA = inv[mt][0], iB = inv[mt][1];
#pragma unroll
            for (int n2 = 0; n2 < 2; n2++) {
                int col = h * 16 + n2 * 8 + 2 * c;
                *(uint32_t*)(smc + S_IN_B + (2 + rA) * 272 + col * 2) =
                    h2(xacc[mt][n2][0] * iA, xacc[mt][n2][1] * iA);
                *(uint32_t*)(smc + S_IN_B + (2 + rB) * 272 + col * 2) =
                    h2(xacc[mt][n2][2] * iB, xacc[mt][n2][3] * iB);
            }
        }
    }
    __syncthreads();

    // ---- output projection (rows t+2, Wo pre-staged), epilogue to gmem ----
    zacc(acc);
    mma_chunk(acc, smb + S_IN_B + 2 * 272 + a_row_off, b_thr);
    epi_g(out + base, bo, acc, lane, m0, ncol0);
}

extern "C" void kernel_launch(void* const* d_in, const int* in_sizes, int n_in,
                              void* d_out, int out_size) {
    (void)in_sizes; (void)n_in; (void)out_size;
    const float* query = (const float*)d_in[0];
    const float* key   = (const float*)d_in[1];
    const float* value = (const float*)d_in[2];
    const int*   mask  = (const int*)d_in[3];
    const float* Wq = (const float*)d_in[4];
    const float* bq = (const float*)d_in[5];
    const float* Wk = (const float*)d_in[6];
    const float* bk = (const float*)d_in[7];
    const float* Wv = (const float*)d_in[8];
    const float* bv = (const float*)d_in[9];
    const float* Wo = (const float*)d_in[10];
    const float* bo = (const float*)d_in[11];
    float* out = (float*)d_out;

    cudaFuncSetAttribute(attn_kernel, cudaFuncAttributeMaxDynamicSharedMemorySize, SMEM_BYTES);
    prep_kernel<<<64, 256>>>(Wq, Wk, Wv, Wo);
    attn_kernel<<<4096, 512, SMEM_BYTES>>>(query, key, value, mask, bq, bk, bv, bo, out);
}

// round 9
// speedup vs baseline: 5.3758x; 1.2590x over previous
#include <cuda_runtime.h>
#include <cuda_fp16.h>
#include <cstdint>

// B=8, N=512, T=64, D=128, H=8, DK=16, K=3.
// TWO (b,n) tiles per CTA (M=128), 512 thr = 16 warps, warp tile 32x32.
// All MMA operands fp16 (11-bit significand == tf32), fp32 accumulate.

// byte offsets in dynamic smem
#define S_IN_B   0          // 136 rows x 136 fp16 (272B/row). rows 0,1,66-69,134,135 zero.
                            // tile0 t -> row t+2, tile1 t -> row t+70
#define S_ST_B   36992      // 32KB: one K=128 chunk of packed B fragments
#define S_QP_B   69760      // 128 x 136 fp16 q tile (rows = global m)
#define S_KP_B   104576     // 2 x 16KB packed K^T B-frags (per tile, per head)
#define S_VP_B   137344     // 2 x 16KB packed V B-frags
#define S_MSK_B  170112     // 64 x ull row masks
#define SMEM_BYTES 170624

// g_pack chunk offsets (uint32 units; each chunk = 8192 uint32 = 32KB)
#define PQ4 0
#define PK4 24576
#define PV4 49152
#define PO4 57344

typedef unsigned long long ull;
__device__ uint32_t g_pack[65536];

// ---------------- PTX helpers ----------------
__device__ __forceinline__ uint32_t smem_u32(const void* p) {
    uint32_t a;
    asm("{ .reg .u64 t; cvta.to.shared.u64 t, %1; cvt.u32.u64 %0, t; }" : "=r"(a) : "l"(p));
    return a;
}
__device__ __forceinline__ uint32_t h2(float lo, float hi) {
    uint32_t r; asm("cvt.rn.f16x2.f32 %0, %1, %2;" : "=r"(r) : "f"(hi), "f"(lo)); return r;
}
__device__ __forceinline__ uint4 lds128(uint32_t a) {
    uint4 v;
    asm volatile("ld.shared.v4.b32 {%0,%1,%2,%3}, [%4];"
                 : "=r"(v.x), "=r"(v.y), "=r"(v.z), "=r"(v.w) : "r"(a));
    return v;
}
__device__ __forceinline__ void ldsm4(uint32_t (&r)[4], uint32_t a) {
    asm volatile("ldmatrix.sync.aligned.m8n8.x4.shared.b16 {%0,%1,%2,%3}, [%4];"
                 : "=r"(r[0]), "=r"(r[1]), "=r"(r[2]), "=r"(r[3]) : "r"(a));
}
__device__ __forceinline__ void mma16(float (&c)[4], const uint32_t (&a)[4],
                                      uint32_t b0, uint32_t b1) {
    asm volatile(
        "mma.sync.aligned.m16n8k16.row.col.f32.f16.f16.f32 "
        "{%0,%1,%2,%3},{%4,%5,%6,%7},{%8,%9},{%0,%1,%2,%3};"
        : "+f"(c[0]), "+f"(c[1]), "+f"(c[2]), "+f"(c[3])
        : "r"(a[0]), "r"(a[1]), "r"(a[2]), "r"(a[3]), "r"(b0), "r"(b1));
}

// ---------------- prep: pack weights as fp16 B-fragments (same as R8) ----------
__global__ void prep_kernel(const float* __restrict__ Wq, const float* __restrict__ Wk,
                            const float* __restrict__ Wv, const float* __restrict__ Wo) {
    int idx = blockIdx.x * blockDim.x + threadIdx.x;   // 16384
    if (idx >= 16384) return;
    const float* W; int base4, within, j = 0, conv; float sc = 1.0f;
    if (idx < 6144)       { W = Wq; j = idx >> 11; within = idx & 2047; base4 = PQ4 / 4 + idx; conv = 1; sc = 0.25f; }
    else if (idx < 12288) { int i2 = idx - 6144; W = Wk; j = i2 >> 11; within = i2 & 2047; base4 = PK4 / 4 + i2; conv = 1; }
    else if (idx < 14336) { int i2 = idx - 12288; W = Wv; within = i2; base4 = PV4 / 4 + i2; conv = 0; }
    else                  { int i2 = idx - 14336; W = Wo; within = i2; base4 = PO4 / 4 + i2; conv = 0; }
    int lane = within & 31, njp = (within >> 5) & 7, ksp = within >> 8;
    int n0 = njp * 16 + (lane >> 2);
    int n1 = n0 + 8;
    int k0 = ksp * 16 + 2 * (lane & 3);
    float w[8];
    if (conv) {
        w[0] = W[(n0 * 128 + k0) * 3 + j];     w[1] = W[(n0 * 128 + k0 + 1) * 3 + j];
        w[2] = W[(n0 * 128 + k0 + 8) * 3 + j]; w[3] = W[(n0 * 128 + k0 + 9) * 3 + j];
        w[4] = W[(n1 * 128 + k0) * 3 + j];     w[5] = W[(n1 * 128 + k0 + 1) * 3 + j];
        w[6] = W[(n1 * 128 + k0 + 8) * 3 + j]; w[7] = W[(n1 * 128 + k0 + 9) * 3 + j];
    } else {
        w[0] = W[n0 * 128 + k0];     w[1] = W[n0 * 128 + k0 + 1];
        w[2] = W[n0 * 128 + k0 + 8]; w[3] = W[n0 * 128 + k0 + 9];
        w[4] = W[n1 * 128 + k0];     w[5] = W[n1 * 128 + k0 + 1];
        w[6] = W[n1 * 128 + k0 + 8]; w[7] = W[n1 * 128 + k0 + 9];
    }
    uint4 o;
    o.x = h2(w[0] * sc, w[1] * sc);
    o.y = h2(w[2] * sc, w[3] * sc);
    o.z = h2(w[4] * sc, w[5] * sc);
    o.w = h2(w[6] * sc, w[7] * sc);
    ((uint4*)g_pack)[base4] = o;
}

// ---------------- building blocks ----------------
__device__ __forceinline__ void load_input(char* smc, const float* __restrict__ g, int tid) {
#pragma unroll
    for (int r = 0; r < 8; r++) {
        int idx = tid + r * 512;                       // 4096 float4 (2 tiles)
        float4 f = *(const float4*)(g + idx * 4);
        int tile = idx >> 11, within = idx & 2047;
        int t = within >> 5, d = (within & 31) * 4;
        int row = (tile ? 70 : 2) + t;
        uint2 v;
        v.x = h2(f.x, f.y);
        v.y = h2(f.z, f.w);
        *(uint2*)(smc + S_IN_B + row * 272 + d * 2) = v;
    }
}
__device__ __forceinline__ void stage_B(char* smc, const uint4* __restrict__ g4, int tid) {
#pragma unroll
    for (int r = 0; r < 4; r++) {
        int idx = tid + r * 512;
        *(uint4*)(smc + S_ST_B + idx * 16) = g4[idx];
    }
}
// one K=128 chunk, warp tile 32x32: acc[msub][nt]
__device__ __forceinline__ void mma_chunk(float (&acc)[2][4][4], uint32_t a0, uint32_t b0) {
#pragma unroll
    for (int ksp = 0; ksp < 8; ksp++) {
        uint32_t A0[4], A1[4];
        ldsm4(A0, a0 + ksp * 32);
        ldsm4(A1, a0 + 16 * 272 + ksp * 32);
        uint4 B01 = lds128(b0 + ksp * 4096);
        uint4 B23 = lds128(b0 + ksp * 4096 + 512);
        mma16(acc[0][0], A0, B01.x, B01.y);
        mma16(acc[0][1], A0, B01.z, B01.w);
        mma16(acc[0][2], A0, B23.x, B23.y);
        mma16(acc[0][3], A0, B23.z, B23.w);
        mma16(acc[1][0], A1, B01.x, B01.y);
        mma16(acc[1][1], A1, B01.z, B01.w);
        mma16(acc[1][2], A1, B23.x, B23.y);
        mma16(acc[1][3], A1, B23.z, B23.w);
    }
}
__device__ __forceinline__ void zacc(float (&acc)[2][4][4]) {
#pragma unroll
    for (int s = 0; s < 2; s++)
#pragma unroll
        for (int i = 0; i < 4; i++)
#pragma unroll
            for (int k = 0; k < 4; k++) acc[s][i][k] = 0.f;
}
// q epilogue -> QP rows = global m (0..127)
__device__ __forceinline__ void epi_q(char* smc, const float* __restrict__ bq,
                                      float (&acc)[2][4][4], int lane, int mg, int ng) {
#pragma unroll
    for (int msub = 0; msub < 2; msub++) {
        int r0 = mg * 32 + msub * 16 + (lane >> 2);
#pragma unroll
        for (int nt = 0; nt < 4; nt++) {
            int col = ng * 32 + nt * 8 + (lane & 3) * 2;
            float2 bb = *(const float2*)(bq + col);
            *(uint32_t*)(smc + S_QP_B + r0 * 272 + col * 2) =
                h2(acc[msub][nt][0] + bb.x * 0.25f, acc[msub][nt][1] + bb.y * 0.25f);
            *(uint32_t*)(smc + S_QP_B + (r0 + 8) * 272 + col * 2) =
                h2(acc[msub][nt][2] + bb.x * 0.25f, acc[msub][nt][3] + bb.y * 0.25f);
        }
    }
}
__device__ __forceinline__ void epi_k(char* smc, const float* __restrict__ bk,
                                      float (&acc)[2][4][4], int lane, int mg, int ng) {
#pragma unroll
    for (int msub = 0; msub < 2; msub++) {
#pragma unroll
        for (int nt = 0; nt < 4; nt++) {
#pragma unroll
            for (int i = 0; i < 4; i++) {
                int s = mg * 32 + msub * 16 + (lane >> 2) + (i >> 1) * 8;
                int col = ng * 32 + nt * 8 + (lane & 3) * 2 + (i & 1);
                int tile = s >> 6, st = s & 63;
                int h = col >> 4, dk = col & 15;
                int ntb = st >> 3, ntp = ntb >> 1;
                int lp = ((st & 7) << 2) | ((dk >> 1) & 3);
                int off = tile * 16384 + ((h * 4 + ntp) * 32 + lp) * 16
                        + (ntb & 1) * 8 + (dk >> 3) * 4 + (dk & 1) * 2;
                *(__half*)(smc + S_KP_B + off) =
                    __float2half_rn(acc[msub][nt][i] + __ldg(bk + col));
            }
        }
    }
}
__device__ __forceinline__ void epi_v(char* smc, const float* __restrict__ bv,
                                      float (&acc)[2][4][4], int lane, int mg, int ng) {
#pragma unroll
    for (int msub = 0; msub < 2; msub++) {
#pragma unroll
        for (int nt = 0; nt < 4; nt++) {
#pragma unroll
            for (int i = 0; i < 4; i++) {
                int s = mg * 32 + msub * 16 + (lane >> 2) + (i >> 1) * 8;
                int col = ng * 32 + nt * 8 + (lane & 3) * 2 + (i & 1);
                int tile = s >> 6, st = s & 63;
                int h = col >> 4, dk = col & 15;
                int ksp = st >> 4, ntv = dk >> 3;
                int lp = ((dk & 7) << 2) | ((st >> 1) & 3);
                int off = tile * 16384 + ((h * 4 + ksp) * 32 + lp) * 16
                        + ntv * 8 + ((st >> 3) & 1) * 4 + (st & 1) * 2;
                *(__half*)(smc + S_VP_B + off) =
                    __float2half_rn(acc[msub][nt][i] + __ldg(bv + col));
            }
        }
    }
}
__device__ __forceinline__ void epi_g(float* __restrict__ dst, const float* __restrict__ bias,
                                      float (&acc)[2][4][4], int lane, int mg, int ng) {
#pragma unroll
    for (int msub = 0; msub < 2; msub++) {
        int r0 = mg * 32 + msub * 16 + (lane >> 2);
#pragma unroll
        for (int nt = 0; nt < 4; nt++) {
            int col = ng * 32 + nt * 8 + (lane & 3) * 2;
            float2 bb = *(const float2*)(bias + col);
            float* d0 = dst + (r0 >> 6) * 8192 + (r0 & 63) * 128 + col;
            float* d1 = dst + ((r0 + 8) >> 6) * 8192 + ((r0 + 8) & 63) * 128 + col;
            *(float2*)d0 = make_float2(acc[msub][nt][0] + bb.x, acc[msub][nt][1] + bb.y);
            *(float2*)d1 = make_float2(acc[msub][nt][2] + bb.x, acc[msub][nt][3] + bb.y);
        }
    }
}

__global__ void __launch_bounds__(512, 1)
attn_kernel(const float* __restrict__ query, const float* __restrict__ key,
            const float* __restrict__ value, const int* __restrict__ mask,
            const float* __restrict__ bq, const float* __restrict__ bk,
            const float* __restrict__ bv, const float* __restrict__ bo,
            float* __restrict__ out)
{
    extern __shared__ char smc[];
    uint32_t smb = smem_u32(smc);
    const int tid = threadIdx.x, lane = tid & 31, wid = tid >> 5;
    const int cta = blockIdx.x, b = cta >> 8;
    const long long base = (long long)cta * 16384;

    const int mg = wid >> 2, ng = wid & 3;
    // A-frag thread base: row t (+j per conv tap), col half
    const int rowbase = (mg & 1) * 32 + (lane & 15) + ((mg >> 1) ? 68 : 0);
    const uint32_t a_thr = smb + S_IN_B + (uint32_t)(rowbase * 272 + (lane >> 4) * 16);
    const uint32_t b_thr = smb + S_ST_B + (uint32_t)(((ng * 2) * 32 + lane) * 16);

    // zero-pad rows 0,1,66,67,68,69,134,135 (68 words each)
    if (tid < 544) {
        int rr = tid / 68, off = tid - rr * 68;
        int row = (rr < 2) ? rr : ((rr < 6) ? (64 + rr) : (128 + rr));
        *(uint32_t*)(smc + S_IN_B + row * 272 + off * 4) = 0u;
    }
    // row bitmasks (shared by both tiles; same b)
    if (tid < 64) {
        ull m = 0;
        const int4* mr = (const int4*)(mask + b * 4096 + tid * 64);
#pragma unroll
        for (int u = 0; u < 16; u++) {
            int4 mm = mr[u];
            ull bits = (ull)(mm.x != 0) | ((ull)(mm.y != 0) << 1) |
                       ((ull)(mm.z != 0) << 2) | ((ull)(mm.w != 0) << 3);
            m |= bits << (u * 4);
        }
        *(ull*)(smc + S_MSK_B + tid * 8) = m;
    }

    float acc[2][4][4];

    // ---- v = dense GEMM (tap 2 = stored rows) -> packed VP ----
    load_input(smc, value + base, tid);
    stage_B(smc, (const uint4*)(g_pack + PV4), tid);
    __syncthreads();
    zacc(acc);
    mma_chunk(acc, a_thr + 2 * 272, b_thr);
    __syncthreads();
    epi_v(smc, bv, acc, lane, mg, ng);

    // ---- q = causal conv (taps 0,1,2) -> QP ----
    load_input(smc, query + base, tid);
    stage_B(smc, (const uint4*)(g_pack + PQ4), tid);
    __syncthreads();
    zacc(acc);
#pragma unroll 1
    for (int j = 0; j < 3; j++) {
        mma_chunk(acc, a_thr + j * 272, b_thr);
        __syncthreads();
        if (j < 2) {
            stage_B(smc, (const uint4*)(g_pack + PQ4 + (j + 1) * 8192), tid);
            __syncthreads();
        }
    }
    epi_q(smc, bq, acc, lane, mg, ng);

    // ---- k = same conv (taps 1,2,3) -> packed KP ----
    load_input(smc, key + base, tid);
    stage_B(smc, (const uint4*)(g_pack + PK4), tid);
    __syncthreads();
    zacc(acc);
#pragma unroll 1
    for (int j = 0; j < 3; j++) {
        mma_chunk(acc, a_thr + (j + 1) * 272, b_thr);
        __syncthreads();
        if (j < 2) {
            stage_B(smc, (const uint4*)(g_pack + PK4 + (j + 1) * 8192), tid);
            __syncthreads();
        }
    }
    epi_k(smc, bk, acc, lane, mg, ng);
    // stage Wo now; attention doesn't touch S_ST
    stage_B(smc, (const uint4*)(g_pack + PO4), tid);
    __syncthreads();

    // ---- attention: warp -> head (wid>>1), row half (wid&1)*32, both tiles ----
    {
        const int h = wid >> 1;
        const int mh = (wid & 1) * 32;
        const int r = lane >> 2, c = lane & 3;
#pragma unroll 1
        for (int tile = 0; tile < 2; tile++) {
            float pa[2][8][4];
#pragma unroll
            for (int mt = 0; mt < 2; mt++)
#pragma unroll
                for (int nt = 0; nt < 8; nt++)
#pragma unroll
                    for (int i = 0; i < 4; i++) pa[mt][nt][i] = 0.f;

            // QK^T
#pragma unroll
            for (int mt = 0; mt < 2; mt++) {
                uint32_t A[4];
                ldsm4(A, smb + S_QP_B
                         + (uint32_t)((tile * 64 + mh + mt * 16 + (lane & 15)) * 272
                                      + h * 32 + (lane >> 4) * 16));
#pragma unroll
                for (int ntp = 0; ntp < 4; ntp++) {
                    uint4 Bf = lds128(smb + S_KP_B
                                      + (uint32_t)(tile * 16384 + ((h * 4 + ntp) * 32 + lane) * 16));
                    mma16(pa[mt][2 * ntp], A, Bf.x, Bf.y);
                    mma16(pa[mt][2 * ntp + 1], A, Bf.z, Bf.w);
                }
            }

            // masked softmax
            float inv[2][2];
#pragma unroll
            for (int mt = 0; mt < 2; mt++) {
                ull mA = *(const ull*)(smc + S_MSK_B + (mh + mt * 16 + r) * 8);
                ull mB = *(const ull*)(smc + S_MSK_B + (mh + mt * 16 + r + 8) * 8);
                float mxA = -3.0e38f, mxB = -3.0e38f;
#pragma unroll
                for (int nt = 0; nt < 8; nt++) {
                    int c0 = nt * 8 + 2 * c, c1 = c0 + 1;
                    float v;
                    v = ((mA >> c0) & 1) ? pa[mt][nt][0] : -1.0e9f; pa[mt][nt][0] = v; mxA = fmaxf(mxA, v);
                    v = ((mA >> c1) & 1) ? pa[mt][nt][1] : -1.0e9f; pa[mt][nt][1] = v; mxA = fmaxf(mxA, v);
                    v = ((mB >> c0) & 1) ? pa[mt][nt][2] : -1.0e9f; pa[mt][nt][2] = v; mxB = fmaxf(mxB, v);
                    v = ((mB >> c1) & 1) ? pa[mt][nt][3] : -1.0e9f; pa[mt][nt][3] = v; mxB = fmaxf(mxB, v);
                }
                mxA = fmaxf(mxA, __shfl_xor_sync(0xffffffffu, mxA, 1));
                mxA = fmaxf(mxA, __shfl_xor_sync(0xffffffffu, mxA, 2));
                mxB = fmaxf(mxB, __shfl_xor_sync(0xffffffffu, mxB, 1));
                mxB = fmaxf(mxB, __shfl_xor_sync(0xffffffffu, mxB, 2));
                float sA = 0.f, sB = 0.f;
#pragma unroll
                for (int nt = 0; nt < 8; nt++) {
                    float e;
                    e = __expf(pa[mt][nt][0] - mxA); pa[mt][nt][0] = e; sA += e;
                    e = __expf(pa[mt][nt][1] - mxA); pa[mt][nt][1] = e; sA += e;
                    e = __expf(pa[mt][nt][2] - mxB); pa[mt][nt][2] = e; sB += e;
                    e = __expf(pa[mt][nt][3] - mxB); pa[mt][nt][3] = e; sB += e;
                }
                sA += __shfl_xor_sync(0xffffffffu, sA, 1);
                sA += __shfl_xor_sync(0xffffffffu, sA, 2);
                sB += __shfl_xor_sync(0xffffffffu, sB, 1);
                sB += __shfl_xor_sync(0xffffffffu, sB, 2);
                inv[mt][0] = 1.0f / sA;
                inv[mt][1] = 1.0f / sB;
            }

            // P @ V
            float xacc[2][2][4];
#pragma unroll
            for (int mt = 0; mt < 2; mt++)
#pragma unroll
                for (int n2 = 0; n2 < 2; n2++)
#pragma unroll
                    for (int i = 0; i < 4; i++) xacc[mt][n2][i] = 0.f;
#pragma unroll
            for (int mt = 0; mt < 2; mt++) {
#pragma unroll
                for (int kp = 0; kp < 4; kp++) {
                    uint32_t A[4];
                    A[0] = h2(pa[mt][2 * kp][0], pa[mt][2 * kp][1]);
                    A[1] = h2(pa[mt][2 * kp][2], pa[mt][2 * kp][3]);
                    A[2] = h2(pa[mt][2 * kp + 1][0], pa[mt][2 * kp + 1][1]);
                    A[3] = h2(pa[mt][2 * kp + 1][2], pa[mt][2 * kp + 1][3]);
                    uint4 V = lds128(smb + S_VP_B
                                     + (uint32_t)(tile * 16384 + ((h * 4 + kp) * 32 + lane) * 16));
                    mma16(xacc[mt][0], A, V.x, V.y);
                    mma16(xacc[mt][1], A, V.z, V.w);
                }
            }

            // x (normalized, fp16) -> S_IN (tile rows), feeds O-proj
            int rowb = tile ? 70 : 2;
#pragma unroll
            for (int mt = 0; mt < 2; mt++) {
                int rA = mh + mt * 16 + r, rB = rA + 8;
                float iA = inv[mt][0], iB = inv[mt][1];
#pragma unroll
                for (int n2 = 0; n2 < 2; n2++) {
                    int col = h * 16 + n2 * 8 + 2 * c;
                    *(uint32_t*)(smc + S_IN_B + (rowb + rA) * 272 + col * 2) =
                        h2(xacc[mt][n2][0] * iA, xacc[mt][n2][1] * iA);
                    *(uint32_t*)(smc + S_IN_B + (rowb + rB) * 272 + col * 2) =
                        h2(xacc[mt][n2][2] * iB, xacc[mt][n2][3] * iB);
                }
            }
        }
    }
    __syncthreads();

    // ---- output projection (tap 2 = stored rows), epilogue to gmem ----
    zacc(acc);
    mma_chunk(acc, a_thr + 2 * 272, b_thr);
    epi_g(out + base, bo, acc, lane, mg, ng);
}

extern "C" void kernel_launch(void* const* d_in, const int* in_sizes, int n_in,
                              void* d_out, int out_size) {
    (void)in_sizes; (void)n_in; (void)out_size;
    const float* query = (const float*)d_in[0];
    const float* key   = (const float*)d_in[1];
    const float* value = (const float*)d_in[2];
    const int*   mask  = (const int*)d_in[3];
    const float* Wq = (const float*)d_in[4];
    const float* bq = (const float*)d_in[5];
    const float* Wk = (const float*)d_in[6];
    const float* bk = (const float*)d_in[7];
    const float* Wv = (const float*)d_in[8];
    const float* bv = (const float*)d_in[9];
    const float* Wo = (const float*)d_in[10];
    const float* bo = (const float*)d_in[11];
    float* out = (float*)d_out;

    cudaFuncSetAttribute(attn_kernel, cudaFuncAttributeMaxDynamicSharedMemorySize, SMEM_BYTES);
    prep_kernel<<<64, 256>>>(Wq, Wk, Wv, Wo);
    attn_kernel<<<2048, 512, SMEM_BYTES>>>(query, key, value, mask, bq, bk, bv, bo, out);
}